// round 2
// baseline (speedup 1.0000x reference)
#include <cuda_runtime.h>
#include <cuda_bf16.h>
#include <math.h>

#define BB 2
#define LL 2048
#define DM 2048
#define NH 16
#define HD 128
#define MROWS (BB*LL)

// Scratch: device globals (no allocation allowed anywhere)
__device__ float g_Q[BB*NH*LL*HD];
__device__ float g_K[BB*NH*LL*HD];
__device__ float g_V[BB*NH*LL*HD];
__device__ float g_AO[MROWS*DM];

// ---------------------------------------------------------------------------
// GEMM: C[M,N] = A[M,K] * W[N,K]^T   (both operands K-contiguous, NT form)
// Tile 128x128, BK=16, 256 threads, 8x8 per thread (split 4+4 across halves).
// MODE 0: plain store to C[M,N]
// MODE 1: permuted store to [B, H, L, HD]  (N-tile == one head since TILE==HD)
// MODE 2: like MODE 1, plus fused RoPE rotation (per-head cos/sin; the
//         reference indexes the rotary cache by head, constant over seq pos,
//         and cos[j] == cos[j+64] because freqs are duplicated).
// ---------------------------------------------------------------------------
template<int MODE>
__global__ void __launch_bounds__(256) gemm_nt(const float* __restrict__ A,
                                               const float* __restrict__ W,
                                               float* __restrict__ C,
                                               const float* __restrict__ cosc,
                                               const float* __restrict__ sinc)
{
    const int K = DM, N = DM;
    __shared__ float As[16][128];
    __shared__ float Bs[16][128];

    const int tid = threadIdx.x;
    const int tx = tid & 15;        // col group
    const int ty = tid >> 4;        // row group
    const int m0 = blockIdx.y * 128;
    const int n0 = blockIdx.x * 128;

    // loader mapping: each thread brings 2 float4 (8 k-values) of one row
    const int arow = tid >> 1;           // 0..127
    const int ak   = (tid & 1) * 8;      // 0 or 8
    const float* Ap = A + (size_t)(m0 + arow) * K + ak;
    const float* Wp = W + (size_t)(n0 + arow) * K + ak;

    float c[8][8];
    #pragma unroll
    for (int i = 0; i < 8; ++i)
        #pragma unroll
        for (int j = 0; j < 8; ++j) c[i][j] = 0.f;

    float4 pa0 = *(const float4*)(Ap + 0);
    float4 pa1 = *(const float4*)(Ap + 4);
    float4 pb0 = *(const float4*)(Wp + 0);
    float4 pb1 = *(const float4*)(Wp + 4);

    for (int kt = 0; kt < K; kt += 16) {
        As[ak+0][arow] = pa0.x; As[ak+1][arow] = pa0.y;
        As[ak+2][arow] = pa0.z; As[ak+3][arow] = pa0.w;
        As[ak+4][arow] = pa1.x; As[ak+5][arow] = pa1.y;
        As[ak+6][arow] = pa1.z; As[ak+7][arow] = pa1.w;
        Bs[ak+0][arow] = pb0.x; Bs[ak+1][arow] = pb0.y;
        Bs[ak+2][arow] = pb0.z; Bs[ak+3][arow] = pb0.w;
        Bs[ak+4][arow] = pb1.x; Bs[ak+5][arow] = pb1.y;
        Bs[ak+6][arow] = pb1.z; Bs[ak+7][arow] = pb1.w;
        __syncthreads();

        if (kt + 16 < K) {
            pa0 = *(const float4*)(Ap + kt + 16);
            pa1 = *(const float4*)(Ap + kt + 20);
            pb0 = *(const float4*)(Wp + kt + 16);
            pb1 = *(const float4*)(Wp + kt + 20);
        }

        #pragma unroll
        for (int k = 0; k < 16; ++k) {
            float4 a0 = *(const float4*)&As[k][ty*4];
            float4 a1 = *(const float4*)&As[k][64 + ty*4];
            float4 b0 = *(const float4*)&Bs[k][tx*4];
            float4 b1 = *(const float4*)&Bs[k][64 + tx*4];
            float av[8] = {a0.x,a0.y,a0.z,a0.w,a1.x,a1.y,a1.z,a1.w};
            float bv[8] = {b0.x,b0.y,b0.z,b0.w,b1.x,b1.y,b1.z,b1.w};
            #pragma unroll
            for (int i = 0; i < 8; ++i)
                #pragma unroll
                for (int j = 0; j < 8; ++j)
                    c[i][j] += av[i] * bv[j];
        }
        __syncthreads();
    }

    // RoPE coefficients (MODE 2): per-head, col pair (tx*4+j, 64+tx*4+j)
    float4 cv, sv;
    if (MODE == 2) {
        int h = n0 >> 7;
        cv = *(const float4*)(cosc + h*HD + tx*4);
        sv = *(const float4*)(sinc + h*HD + tx*4);
    }

    #pragma unroll
    for (int i = 0; i < 8; ++i) {
        int row = m0 + ((i < 4) ? (ty*4 + i) : (64 + ty*4 + (i-4)));
        float4 v0 = make_float4(c[i][0], c[i][1], c[i][2], c[i][3]);
        float4 v1 = make_float4(c[i][4], c[i][5], c[i][6], c[i][7]);
        if (MODE == 0) {
            float* dst = C + (size_t)row * N + n0;
            *(float4*)(dst + tx*4)      = v0;
            *(float4*)(dst + 64 + tx*4) = v1;
        } else {
            if (MODE == 2) {
                // q'[j]    = q[j]*cos - q[j+64]*sin
                // q'[j+64] = q[j+64]*cos + q[j]*sin
                float4 n0v, n1v;
                n0v.x = v0.x*cv.x - v1.x*sv.x;  n1v.x = v1.x*cv.x + v0.x*sv.x;
                n0v.y = v0.y*cv.y - v1.y*sv.y;  n1v.y = v1.y*cv.y + v0.y*sv.y;
                n0v.z = v0.z*cv.z - v1.z*sv.z;  n1v.z = v1.z*cv.z + v0.z*sv.z;
                n0v.w = v0.w*cv.w - v1.w*sv.w;  n1v.w = v1.w*cv.w + v0.w*sv.w;
                v0 = n0v; v1 = n1v;
            }
            // row = b*L + l ; head = n0/128 ; store to [b][h][l][hd]
            int b = row >> 11;
            int l = row & (LL - 1);
            int h = n0 >> 7;
            float* dst = C + (((size_t)(b*NH + h))*LL + l) * HD;
            *(float4*)(dst + tx*4)      = v0;
            *(float4*)(dst + 64 + tx*4) = v1;
        }
    }
}

// ---------------------------------------------------------------------------
// Flash attention, fp32, causal + padding mask.
// Block = (q-tile of 64) x (head) x (batch). 256 threads.
// Phase 1: S(64x64) = Qt·Ktᵀ, 4x4 per thread. Online softmax w/ half-warp shfl.
// Phase 2: O(64x128) += P·Vt, 4x8 per thread.
// Output stored [B, L, H, HD] so the final projection is a plain NT GEMM.
// ---------------------------------------------------------------------------
#define ATTN_SMEM ((128*64 + 128*64 + 64*128 + 64*68) * 4)

__global__ void __launch_bounds__(256) attn_kernel(
    const float* __restrict__ gQ, const float* __restrict__ gK,
    const float* __restrict__ gV, const int* __restrict__ mask,
    float* __restrict__ gO)
{
    extern __shared__ float sm[];
    float* Qs = sm;            // [d][row]  128x64 (transposed)
    float* Ks = sm + 8192;     // [d][col]  128x64 (transposed)
    float* Vs = sm + 16384;    // [row][d]  64x128
    float* Ps = sm + 24576;    // [col][row] 64x68 (padded)

    const int tid = threadIdx.x;
    const int tx = tid & 15;
    const int ty = tid >> 4;
    const int q0 = blockIdx.x * 64;
    const int h  = blockIdx.y;
    const int b  = blockIdx.z;

    const size_t hb = ((size_t)(b*NH + h)) * LL * HD;
    const float* Qb = gQ + hb;
    const float* Kb = gK + hb;
    const float* Vb = gV + hb;
    const float scale = 0.08838834764831845f;   // 1/sqrt(128)

    // Load Q tile (scaled), transposed into Qs[d][row]
    #pragma unroll
    for (int t = 0; t < 8; ++t) {
        int i   = tid + t*256;        // 0..2047
        int row = i >> 5;
        int dq  = (i & 31) * 4;
        float4 v = *(const float4*)(Qb + (size_t)(q0+row)*HD + dq);
        Qs[(dq+0)*64 + row] = v.x * scale;
        Qs[(dq+1)*64 + row] = v.y * scale;
        Qs[(dq+2)*64 + row] = v.z * scale;
        Qs[(dq+3)*64 + row] = v.w * scale;
    }

    float m_i[4], l_i[4], o[4][8];
    #pragma unroll
    for (int i = 0; i < 4; ++i) {
        m_i[i] = -1e30f; l_i[i] = 0.f;
        #pragma unroll
        for (int j = 0; j < 8; ++j) o[i][j] = 0.f;
    }

    const int ktmax = q0 >> 6;
    for (int kt = 0; kt <= ktmax; ++kt) {
        const int k0 = kt * 64;
        __syncthreads();   // prev iter done with Ks/Vs/Ps; Q visible on iter 0

        #pragma unroll
        for (int t = 0; t < 8; ++t) {
            int i   = tid + t*256;
            int row = i >> 5;
            int dq  = (i & 31) * 4;
            float4 kv = *(const float4*)(Kb + (size_t)(k0+row)*HD + dq);
            Ks[(dq+0)*64 + row] = kv.x;
            Ks[(dq+1)*64 + row] = kv.y;
            Ks[(dq+2)*64 + row] = kv.z;
            Ks[(dq+3)*64 + row] = kv.w;
            *(float4*)(Vs + row*HD + dq) =
                *(const float4*)(Vb + (size_t)(k0+row)*HD + dq);
        }
        __syncthreads();

        // S = Q·Kᵀ (scaled already)
        float s[4][4];
        #pragma unroll
        for (int i = 0; i < 4; ++i)
            #pragma unroll
            for (int j = 0; j < 4; ++j) s[i][j] = 0.f;

        #pragma unroll 8
        for (int d = 0; d < HD; ++d) {
            float4 a  = *(const float4*)&Qs[d*64 + ty*4];
            float4 bq = *(const float4*)&Ks[d*64 + tx*4];
            float av[4] = {a.x, a.y, a.z, a.w};
            float bv[4] = {bq.x, bq.y, bq.z, bq.w};
            #pragma unroll
            for (int i = 0; i < 4; ++i)
                #pragma unroll
                for (int j = 0; j < 4; ++j)
                    s[i][j] += av[i] * bv[j];
        }

        // masks
        bool okc[4];
        #pragma unroll
        for (int j = 0; j < 4; ++j)
            okc[j] = (mask[b*LL + k0 + tx*4 + j] != 0);

        // online softmax (rows owned by the 16 threads sharing ty == half-warp)
        #pragma unroll
        for (int i = 0; i < 4; ++i) {
            const int qr = q0 + ty*4 + i;
            float tm = -1e30f;
            #pragma unroll
            for (int j = 0; j < 4; ++j) {
                int kc = k0 + tx*4 + j;
                float sv = (kc <= qr && okc[j]) ? s[i][j] : -1e15f;
                s[i][j] = sv;
                tm = fmaxf(tm, sv);
            }
            #pragma unroll
            for (int off = 8; off > 0; off >>= 1)
                tm = fmaxf(tm, __shfl_xor_sync(0xffffffffu, tm, off));
            float mnew = fmaxf(m_i[i], tm);
            float sc   = __expf(m_i[i] - mnew);
            float rs   = 0.f;
            float p[4];
            #pragma unroll
            for (int j = 0; j < 4; ++j) {
                p[j] = __expf(s[i][j] - mnew);
                rs += p[j];
            }
            #pragma unroll
            for (int off = 8; off > 0; off >>= 1)
                rs += __shfl_xor_sync(0xffffffffu, rs, off);
            l_i[i] = l_i[i] * sc + rs;
            m_i[i] = mnew;
            #pragma unroll
            for (int j = 0; j < 8; ++j) o[i][j] *= sc;
            #pragma unroll
            for (int j = 0; j < 4; ++j)
                Ps[(tx*4 + j)*68 + ty*4 + i] = p[j];
        }
        __syncthreads();

        // O += P·V
        #pragma unroll 4
        for (int j = 0; j < 64; ++j) {
            float4 a  = *(const float4*)&Ps[j*68 + ty*4];
            float4 v0 = *(const float4*)&Vs[j*HD + tx*8];
            float4 v1 = *(const float4*)&Vs[j*HD + tx*8 + 4];
            float av[4] = {a.x, a.y, a.z, a.w};
            float vv[8] = {v0.x,v0.y,v0.z,v0.w,v1.x,v1.y,v1.z,v1.w};
            #pragma unroll
            for (int i = 0; i < 4; ++i)
                #pragma unroll
                for (int jj = 0; jj < 8; ++jj)
                    o[i][jj] += av[i] * vv[jj];
        }
    }

    // epilogue: write [B, L, H, HD]
    #pragma unroll
    for (int i = 0; i < 4; ++i) {
        float inv = 1.0f / l_i[i];
        int lrow = q0 + ty*4 + i;
        float* dst = gO + (((size_t)(b*LL + lrow))*NH + h)*HD + tx*8;
        float4 r0 = make_float4(o[i][0]*inv, o[i][1]*inv, o[i][2]*inv, o[i][3]*inv);
        float4 r1 = make_float4(o[i][4]*inv, o[i][5]*inv, o[i][6]*inv, o[i][7]*inv);
        *(float4*)(dst)     = r0;
        *(float4*)(dst + 4) = r1;
    }
}

// ---------------------------------------------------------------------------
extern "C" void kernel_launch(void* const* d_in, const int* in_sizes, int n_in,
                              void* d_out, int out_size)
{
    const float* hidden = (const float*)d_in[0];
    const int*   mask   = (const int*)  d_in[1];
    const float* Wq     = (const float*)d_in[2];
    const float* Wk     = (const float*)d_in[3];
    const float* Wv     = (const float*)d_in[4];
    const float* Wo     = (const float*)d_in[5];
    const float* cosc   = (const float*)d_in[6];
    const float* sinc   = (const float*)d_in[7];
    float* out = (float*)d_out;

    float *Qp, *Kp, *Vp, *AOp;
    cudaGetSymbolAddress((void**)&Qp,  g_Q);
    cudaGetSymbolAddress((void**)&Kp,  g_K);
    cudaGetSymbolAddress((void**)&Vp,  g_V);
    cudaGetSymbolAddress((void**)&AOp, g_AO);

    dim3 gg(DM/128, MROWS/128);
    gemm_nt<2><<<gg, 256>>>(hidden, Wq, Qp, cosc, sinc);  // Q proj + RoPE
    gemm_nt<2><<<gg, 256>>>(hidden, Wk, Kp, cosc, sinc);  // K proj + RoPE
    gemm_nt<1><<<gg, 256>>>(hidden, Wv, Vp, nullptr, nullptr);

    cudaFuncSetAttribute(attn_kernel,
                         cudaFuncAttributeMaxDynamicSharedMemorySize, ATTN_SMEM);
    dim3 ga(LL/64, NH, BB);
    attn_kernel<<<ga, 256, ATTN_SMEM>>>(Qp, Kp, Vp, mask, AOp);

    gemm_nt<0><<<gg, 256>>>(AOp, Wo, out, nullptr, nullptr);
}

// round 4
// speedup vs baseline: 1.3988x; 1.3988x over previous
#include <cuda_runtime.h>
#include <cuda_bf16.h>
#include <cstdint>
#include <math.h>

#define BB 2
#define LL 2048
#define DM 2048
#define NH 16
#define HD 128
#define MROWS (BB*LL)   // 4096

// ---------------------------------------------------------------- scratch ---
__device__ float g_Q[BB*NH*LL*HD];
__device__ float g_K[BB*NH*LL*HD];
__device__ float g_V[BB*NH*LL*HD];
__device__ float g_AO[MROWS*DM];
__device__ __nv_bfloat16 g_Ah[MROWS*DM];
__device__ __nv_bfloat16 g_Al[MROWS*DM];
__device__ __nv_bfloat16 g_Wh[DM*DM];
__device__ __nv_bfloat16 g_Wl[DM*DM];

// ------------------------------------------------------------ ptx helpers ---
__device__ __forceinline__ uint32_t smem_u32(const void* p) {
    uint32_t a;
    asm("{ .reg .u64 t; cvta.to.shared.u64 t, %1; cvt.u32.u64 %0, t; }"
        : "=r"(a) : "l"(p));
    return a;
}
__device__ __forceinline__ void cp16(uint32_t d, const void* s) {
    asm volatile("cp.async.cg.shared.global [%0], [%1], 16;" :: "r"(d), "l"(s));
}
__device__ __forceinline__ void cp_commit() {
    asm volatile("cp.async.commit_group;" ::: "memory");
}
template<int N> __device__ __forceinline__ void cp_wait() {
    asm volatile("cp.async.wait_group %0;" :: "n"(N) : "memory");
}
__device__ __forceinline__ void ldm4(uint32_t* r, uint32_t addr) {
    asm volatile("ldmatrix.sync.aligned.m8n8.x4.shared.b16 {%0,%1,%2,%3}, [%4];"
                 : "=r"(r[0]), "=r"(r[1]), "=r"(r[2]), "=r"(r[3]) : "r"(addr));
}
__device__ __forceinline__ void mma16816(float* c, const uint32_t* a,
                                         const uint32_t* b) {
    asm volatile(
        "mma.sync.aligned.m16n8k16.row.col.f32.bf16.bf16.f32 "
        "{%0,%1,%2,%3}, {%4,%5,%6,%7}, {%8,%9}, {%0,%1,%2,%3};"
        : "+f"(c[0]), "+f"(c[1]), "+f"(c[2]), "+f"(c[3])
        : "r"(a[0]), "r"(a[1]), "r"(a[2]), "r"(a[3]), "r"(b[0]), "r"(b[1]));
}

// ------------------------------------------------------------ split fp32 ----
// a = hi + lo  (both bf16, RN); |lo| <= 2^-9 |a|
__global__ void __launch_bounds__(256) split_kernel(
    const float* __restrict__ src, __nv_bfloat16* __restrict__ hi,
    __nv_bfloat16* __restrict__ lo, int n4)
{
    int i = blockIdx.x * blockDim.x + threadIdx.x;
    if (i >= n4) return;
    float4 a = ((const float4*)src)[i];
    __nv_bfloat16 h0 = __float2bfloat16(a.x);
    __nv_bfloat16 h1 = __float2bfloat16(a.y);
    __nv_bfloat16 h2 = __float2bfloat16(a.z);
    __nv_bfloat16 h3 = __float2bfloat16(a.w);
    __nv_bfloat16 l0 = __float2bfloat16(a.x - __bfloat162float(h0));
    __nv_bfloat16 l1 = __float2bfloat16(a.y - __bfloat162float(h1));
    __nv_bfloat16 l2 = __float2bfloat16(a.z - __bfloat162float(h2));
    __nv_bfloat16 l3 = __float2bfloat16(a.w - __bfloat162float(h3));
    ((__nv_bfloat162*)hi)[2*i]   = __nv_bfloat162(h0, h1);
    ((__nv_bfloat162*)hi)[2*i+1] = __nv_bfloat162(h2, h3);
    ((__nv_bfloat162*)lo)[2*i]   = __nv_bfloat162(l0, l1);
    ((__nv_bfloat162*)lo)[2*i+1] = __nv_bfloat162(l2, l3);
}

// --------------------------------------------------- mma.sync bf16 GEMM ----
// C[M,N] = A[M,K] * W[N,K]^T ; A = Ah+Al, W = Wh+Wl ; C ~= AhWh + AlWh + AhWl.
// CTA tile 128x128, BK=32, 256 threads (8 warps, 2x4), warp tile 64x32.
// 3-stage cp.async pipeline. Epilogue stages C via smem for RoPE/permute.
// MODE 0: C[row][n]   MODE 1: [B,H,L,HD] permute   MODE 2: MODE1 + RoPE
#define SROWB 80                       // 32 bf16 + 8 pad = 80 bytes/row
#define OPB   (128*SROWB)              // 10240 bytes per operand tile
#define STGB  (4*OPB)                  // 40960 bytes per stage
#define GSTG  3
#define GSMEM (GSTG*STGB)              // 122880 (>= 128*132*4 epilogue)

template<int MODE>
__global__ void __launch_bounds__(256) gemm_mma(
    const __nv_bfloat16* __restrict__ Ah, const __nv_bfloat16* __restrict__ Al,
    const __nv_bfloat16* __restrict__ Bh, const __nv_bfloat16* __restrict__ Bl,
    float* __restrict__ C,
    const float* __restrict__ cosc, const float* __restrict__ sinc)
{
    extern __shared__ char smem[];
    const uint32_t sb = smem_u32(smem);
    const int tid  = threadIdx.x;
    const int lane = tid & 31, wid = tid >> 5;
    const int wm = wid >> 2, wn = wid & 3;         // warp grid 2x4
    const int m0 = blockIdx.y * 128, n0 = blockIdx.x * 128;
    const int S = DM / 32;                         // 64 k-stages

    // loader: each thread moves 32B (2x cp16) per operand per stage
    const int lrow = tid >> 1;
    const int lseg = (tid & 1) * 2;                // 16B-chunk index 0 or 2
    const size_t ga = (size_t)(m0 + lrow) * DM + lseg * 8;
    const size_t gb = (size_t)(n0 + lrow) * DM + lseg * 8;
    const uint32_t sd = lrow * SROWB + lseg * 16;

    float acc[4][4][4];
    #pragma unroll
    for (int i = 0; i < 4; ++i)
        #pragma unroll
        for (int j = 0; j < 4; ++j)
            #pragma unroll
            for (int q = 0; q < 4; ++q) acc[i][j][q] = 0.f;

    auto load_stage = [&](int s) {
        const int k0 = s * 32;
        const uint32_t base = sb + (s % GSTG) * STGB;
        const char* pah = (const char*)(Ah + ga + k0);
        const char* pal = (const char*)(Al + ga + k0);
        const char* pbh = (const char*)(Bh + gb + k0);
        const char* pbl = (const char*)(Bl + gb + k0);
        cp16(base +        sd,      pah);      cp16(base +        sd + 16, pah + 16);
        cp16(base + OPB  + sd,      pal);      cp16(base + OPB  + sd + 16, pal + 16);
        cp16(base + 2*OPB + sd,     pbh);      cp16(base + 2*OPB + sd + 16, pbh + 16);
        cp16(base + 3*OPB + sd,     pbl);      cp16(base + 3*OPB + sd + 16, pbl + 16);
        cp_commit();
    };

    load_stage(0);
    load_stage(1);

    // ldmatrix address offsets (within an operand tile)
    // A frag (m16k16): row = lane&15, koff8 = lane>>4
    const uint32_t a_off = (uint32_t)((wm*64 + (lane & 15)) * SROWB + (lane >> 4) * 16);
    // B frag (two n8-tiles x k16): n = ((lane>>4)&1)*8 + (lane&7), koff8 = (lane>>3)&1
    const uint32_t b_off = (uint32_t)((wn*32 + ((lane >> 4) & 1)*8 + (lane & 7)) * SROWB
                                      + ((lane >> 3) & 1) * 16);

    for (int s = 0; s < S; ++s) {
        if (s == S - 1) cp_wait<0>(); else cp_wait<1>();
        __syncthreads();
        if (s + 2 < S) load_stage(s + 2);

        const uint32_t base = sb + (s % GSTG) * STGB;
        #pragma unroll
        for (int kk = 0; kk < 2; ++kk) {
            const uint32_t kadd = kk * 32;   // 16 bf16 = 32 bytes
            uint32_t ah[4][4], bh[2][4];
            #pragma unroll
            for (int i = 0; i < 4; ++i)
                ldm4(ah[i], base + a_off + i*16*SROWB + kadd);
            #pragma unroll
            for (int p = 0; p < 2; ++p)
                ldm4(bh[p], base + 2*OPB + b_off + p*16*SROWB + kadd);
            #pragma unroll
            for (int i = 0; i < 4; ++i)
                #pragma unroll
                for (int j = 0; j < 4; ++j)
                    mma16816(acc[i][j], ah[i], &bh[j >> 1][(j & 1) * 2]);

            {   // Al x Bh
                uint32_t al[4][4];
                #pragma unroll
                for (int i = 0; i < 4; ++i)
                    ldm4(al[i], base + OPB + a_off + i*16*SROWB + kadd);
                #pragma unroll
                for (int i = 0; i < 4; ++i)
                    #pragma unroll
                    for (int j = 0; j < 4; ++j)
                        mma16816(acc[i][j], al[i], &bh[j >> 1][(j & 1) * 2]);
            }
            {   // Ah x Bl
                uint32_t bl[2][4];
                #pragma unroll
                for (int p = 0; p < 2; ++p)
                    ldm4(bl[p], base + 3*OPB + b_off + p*16*SROWB + kadd);
                #pragma unroll
                for (int i = 0; i < 4; ++i)
                    #pragma unroll
                    for (int j = 0; j < 4; ++j)
                        mma16816(acc[i][j], ah[i], &bl[j >> 1][(j & 1) * 2]);
            }
        }
    }

    // ---- epilogue: stage C tile through smem (stride 132 floats) ----
    __syncthreads();
    float* Cs = (float*)smem;
    const int frow = wm*64 + (lane >> 2);
    const int fcol = wn*32 + (lane & 3) * 2;
    #pragma unroll
    for (int i = 0; i < 4; ++i)
        #pragma unroll
        for (int j = 0; j < 4; ++j) {
            float2 lo = make_float2(acc[i][j][0], acc[i][j][1]);
            float2 hi = make_float2(acc[i][j][2], acc[i][j][3]);
            *(float2*)&Cs[(frow + i*16    )*132 + fcol + j*8] = lo;
            *(float2*)&Cs[(frow + i*16 + 8)*132 + fcol + j*8] = hi;
        }
    __syncthreads();

    const int row  = tid >> 1;
    const int half = tid & 1;                    // cols [half*32, +32) & +64
    const int grow = m0 + row;
    float* dst;
    if (MODE == 0) {
        dst = C + (size_t)grow * DM + n0;
    } else {
        int bb = grow >> 11, l = grow & (LL - 1), h = n0 >> 7;
        dst = C + (((size_t)(bb * NH + h)) * LL + l) * HD;
    }
    const int h = n0 >> 7;

    #pragma unroll
    for (int c0 = 0; c0 < 32; c0 += 4) {
        const int col = half*32 + c0;
        float4 v0 = *(float4*)&Cs[row*132 + col];
        float4 v1 = *(float4*)&Cs[row*132 + col + 64];
        if (MODE == 2) {
            float o0[4], o1[4];
            float vv0[4] = {v0.x, v0.y, v0.z, v0.w};
            float vv1[4] = {v1.x, v1.y, v1.z, v1.w};
            #pragma unroll
            for (int q = 0; q < 4; ++q) {
                float c1 = cosc[h*HD + col + q];
                float s1 = sinc[h*HD + col + q];
                float c2 = cosc[h*HD + col + q + 64];
                float s2 = sinc[h*HD + col + q + 64];
                o0[q] = vv0[q]*c1 - vv1[q]*s1;
                o1[q] = vv1[q]*c2 + vv0[q]*s2;
            }
            v0 = make_float4(o0[0], o0[1], o0[2], o0[3]);
            v1 = make_float4(o1[0], o1[1], o1[2], o1[3]);
        }
        *(float4*)(dst + col)      = v0;
        *(float4*)(dst + col + 64) = v1;
    }
}

// ---------------------------------------------------------------------------
// Flash attention, fp32, causal + padding mask (unchanged; passed in R2).
// ---------------------------------------------------------------------------
#define ATTN_SMEM ((128*64 + 128*64 + 64*128 + 64*68) * 4)

__global__ void __launch_bounds__(256) attn_kernel(
    const float* __restrict__ gQ, const float* __restrict__ gK,
    const float* __restrict__ gV, const int* __restrict__ mask,
    float* __restrict__ gO)
{
    extern __shared__ float sm[];
    float* Qs = sm;            // [d][row]  128x64 (transposed)
    float* Ks = sm + 8192;     // [d][col]  128x64 (transposed)
    float* Vs = sm + 16384;    // [row][d]  64x128
    float* Ps = sm + 24576;    // [col][row] 64x68 (padded)

    const int tid = threadIdx.x;
    const int tx = tid & 15;
    const int ty = tid >> 4;
    const int q0 = blockIdx.x * 64;
    const int h  = blockIdx.y;
    const int b  = blockIdx.z;

    const size_t hb = ((size_t)(b*NH + h)) * LL * HD;
    const float* Qb = gQ + hb;
    const float* Kb = gK + hb;
    const float* Vb = gV + hb;
    const float scale = 0.08838834764831845f;

    #pragma unroll
    for (int t = 0; t < 8; ++t) {
        int i   = tid + t*256;
        int row = i >> 5;
        int dq  = (i & 31) * 4;
        float4 v = *(const float4*)(Qb + (size_t)(q0+row)*HD + dq);
        Qs[(dq+0)*64 + row] = v.x * scale;
        Qs[(dq+1)*64 + row] = v.y * scale;
        Qs[(dq+2)*64 + row] = v.z * scale;
        Qs[(dq+3)*64 + row] = v.w * scale;
    }

    float m_i[4], l_i[4], o[4][8];
    #pragma unroll
    for (int i = 0; i < 4; ++i) {
        m_i[i] = -1e30f; l_i[i] = 0.f;
        #pragma unroll
        for (int j = 0; j < 8; ++j) o[i][j] = 0.f;
    }

    const int ktmax = q0 >> 6;
    for (int kt = 0; kt <= ktmax; ++kt) {
        const int k0 = kt * 64;
        __syncthreads();

        #pragma unroll
        for (int t = 0; t < 8; ++t) {
            int i   = tid + t*256;
            int row = i >> 5;
            int dq  = (i & 31) * 4;
            float4 kv = *(const float4*)(Kb + (size_t)(k0+row)*HD + dq);
            Ks[(dq+0)*64 + row] = kv.x;
            Ks[(dq+1)*64 + row] = kv.y;
            Ks[(dq+2)*64 + row] = kv.z;
            Ks[(dq+3)*64 + row] = kv.w;
            *(float4*)(Vs + row*HD + dq) =
                *(const float4*)(Vb + (size_t)(k0+row)*HD + dq);
        }
        __syncthreads();

        float s[4][4];
        #pragma unroll
        for (int i = 0; i < 4; ++i)
            #pragma unroll
            for (int j = 0; j < 4; ++j) s[i][j] = 0.f;

        #pragma unroll 8
        for (int d = 0; d < HD; ++d) {
            float4 a  = *(const float4*)&Qs[d*64 + ty*4];
            float4 bq = *(const float4*)&Ks[d*64 + tx*4];
            float av[4] = {a.x, a.y, a.z, a.w};
            float bv[4] = {bq.x, bq.y, bq.z, bq.w};
            #pragma unroll
            for (int i = 0; i < 4; ++i)
                #pragma unroll
                for (int j = 0; j < 4; ++j)
                    s[i][j] += av[i] * bv[j];
        }

        bool okc[4];
        #pragma unroll
        for (int j = 0; j < 4; ++j)
            okc[j] = (mask[b*LL + k0 + tx*4 + j] != 0);

        #pragma unroll
        for (int i = 0; i < 4; ++i) {
            const int qr = q0 + ty*4 + i;
            float tm = -1e30f;
            #pragma unroll
            for (int j = 0; j < 4; ++j) {
                int kc = k0 + tx*4 + j;
                float sv = (kc <= qr && okc[j]) ? s[i][j] : -1e15f;
                s[i][j] = sv;
                tm = fmaxf(tm, sv);
            }
            #pragma unroll
            for (int off = 8; off > 0; off >>= 1)
                tm = fmaxf(tm, __shfl_xor_sync(0xffffffffu, tm, off));
            float mnew = fmaxf(m_i[i], tm);
            float sc   = __expf(m_i[i] - mnew);
            float rs   = 0.f;
            float p[4];
            #pragma unroll
            for (int j = 0; j < 4; ++j) {
                p[j] = __expf(s[i][j] - mnew);
                rs += p[j];
            }
            #pragma unroll
            for (int off = 8; off > 0; off >>= 1)
                rs += __shfl_xor_sync(0xffffffffu, rs, off);
            l_i[i] = l_i[i] * sc + rs;
            m_i[i] = mnew;
            #pragma unroll
            for (int j = 0; j < 8; ++j) o[i][j] *= sc;
            #pragma unroll
            for (int j = 0; j < 4; ++j)
                Ps[(tx*4 + j)*68 + ty*4 + i] = p[j];
        }
        __syncthreads();

        #pragma unroll 4
        for (int j = 0; j < 64; ++j) {
            float4 a  = *(const float4*)&Ps[j*68 + ty*4];
            float4 v0 = *(const float4*)&Vs[j*HD + tx*8];
            float4 v1 = *(const float4*)&Vs[j*HD + tx*8 + 4];
            float av[4] = {a.x, a.y, a.z, a.w};
            float vv[8] = {v0.x,v0.y,v0.z,v0.w,v1.x,v1.y,v1.z,v1.w};
            #pragma unroll
            for (int i = 0; i < 4; ++i)
                #pragma unroll
                for (int jj = 0; jj < 8; ++jj)
                    o[i][jj] += av[i] * vv[jj];
        }
    }

    #pragma unroll
    for (int i = 0; i < 4; ++i) {
        float inv = 1.0f / l_i[i];
        int lrow = q0 + ty*4 + i;
        float* dst = gO + (((size_t)(b*LL + lrow))*NH + h)*HD + tx*8;
        *(float4*)(dst)     = make_float4(o[i][0]*inv, o[i][1]*inv, o[i][2]*inv, o[i][3]*inv);
        *(float4*)(dst + 4) = make_float4(o[i][4]*inv, o[i][5]*inv, o[i][6]*inv, o[i][7]*inv);
    }
}

// ---------------------------------------------------------------------------
extern "C" void kernel_launch(void* const* d_in, const int* in_sizes, int n_in,
                              void* d_out, int out_size)
{
    const float* hidden = (const float*)d_in[0];
    const int*   mask   = (const int*)  d_in[1];
    const float* Wq     = (const float*)d_in[2];
    const float* Wk     = (const float*)d_in[3];
    const float* Wv     = (const float*)d_in[4];
    const float* Wo     = (const float*)d_in[5];
    const float* cosc   = (const float*)d_in[6];
    const float* sinc   = (const float*)d_in[7];
    float* out = (float*)d_out;

    float *Qp, *Kp, *Vp, *AOp;
    __nv_bfloat16 *Ahp, *Alp, *Whp, *Wlp;
    cudaGetSymbolAddress((void**)&Qp,  g_Q);
    cudaGetSymbolAddress((void**)&Kp,  g_K);
    cudaGetSymbolAddress((void**)&Vp,  g_V);
    cudaGetSymbolAddress((void**)&AOp, g_AO);
    cudaGetSymbolAddress((void**)&Ahp, g_Ah);
    cudaGetSymbolAddress((void**)&Alp, g_Al);
    cudaGetSymbolAddress((void**)&Whp, g_Wh);
    cudaGetSymbolAddress((void**)&Wlp, g_Wl);

    cudaFuncSetAttribute(gemm_mma<0>, cudaFuncAttributeMaxDynamicSharedMemorySize, GSMEM);
    cudaFuncSetAttribute(gemm_mma<1>, cudaFuncAttributeMaxDynamicSharedMemorySize, GSMEM);
    cudaFuncSetAttribute(gemm_mma<2>, cudaFuncAttributeMaxDynamicSharedMemorySize, GSMEM);
    cudaFuncSetAttribute(attn_kernel, cudaFuncAttributeMaxDynamicSharedMemorySize, ATTN_SMEM);

    const int nA4 = MROWS*DM/4, nW4 = DM*DM/4;
    dim3 gg(DM/128, MROWS/128);

    split_kernel<<<(nA4+255)/256, 256>>>(hidden, Ahp, Alp, nA4);

    split_kernel<<<(nW4+255)/256, 256>>>(Wq, Whp, Wlp, nW4);
    gemm_mma<2><<<gg, 256, GSMEM>>>(Ahp, Alp, Whp, Wlp, Qp, cosc, sinc);

    split_kernel<<<(nW4+255)/256, 256>>>(Wk, Whp, Wlp, nW4);
    gemm_mma<2><<<gg, 256, GSMEM>>>(Ahp, Alp, Whp, Wlp, Kp, cosc, sinc);

    split_kernel<<<(nW4+255)/256, 256>>>(Wv, Whp, Wlp, nW4);
    gemm_mma<1><<<gg, 256, GSMEM>>>(Ahp, Alp, Whp, Wlp, Vp, nullptr, nullptr);

    dim3 ga(LL/64, NH, BB);
    attn_kernel<<<ga, 256, ATTN_SMEM>>>(Qp, Kp, Vp, mask, AOp);

    split_kernel<<<(nA4+255)/256, 256>>>(AOp, Ahp, Alp, nA4);
    split_kernel<<<(nW4+255)/256, 256>>>(Wo, Whp, Wlp, nW4);
    gemm_mma<0><<<gg, 256, GSMEM>>>(Ahp, Alp, Whp, Wlp, out, nullptr, nullptr);
}

// round 7
// speedup vs baseline: 2.1898x; 1.5655x over previous
#include <cuda_runtime.h>
#include <cuda_bf16.h>
#include <cstdint>
#include <math.h>

#define BB 2
#define LL 2048
#define DM 2048
#define NH 16
#define HD 128
#define MROWS (BB*LL)   // 4096

// ---------------------------------------------------------------- scratch ---
__device__ __nv_bfloat16 g_Ah[MROWS*DM];
__device__ __nv_bfloat16 g_Al[MROWS*DM];
__device__ __nv_bfloat16 g_Wh[DM*DM];
__device__ __nv_bfloat16 g_Wl[DM*DM];
__device__ __nv_bfloat16 g_Qh[MROWS*DM];
__device__ __nv_bfloat16 g_Ql[MROWS*DM];
__device__ __nv_bfloat16 g_Kh[MROWS*DM];
__device__ __nv_bfloat16 g_Kl[MROWS*DM];
__device__ __nv_bfloat16 g_Vh[MROWS*DM];
__device__ __nv_bfloat16 g_Vl[MROWS*DM];

// ------------------------------------------------------------ ptx helpers ---
__device__ __forceinline__ uint32_t smem_u32(const void* p) {
    uint32_t a;
    asm("{ .reg .u64 t; cvta.to.shared.u64 t, %1; cvt.u32.u64 %0, t; }"
        : "=r"(a) : "l"(p));
    return a;
}
__device__ __forceinline__ void cp16(uint32_t d, const void* s) {
    asm volatile("cp.async.cg.shared.global [%0], [%1], 16;" :: "r"(d), "l"(s));
}
__device__ __forceinline__ void cp_commit() {
    asm volatile("cp.async.commit_group;" ::: "memory");
}
template<int N> __device__ __forceinline__ void cp_wait() {
    asm volatile("cp.async.wait_group %0;" :: "n"(N) : "memory");
}
__device__ __forceinline__ void ldm4(uint32_t* r, uint32_t addr) {
    asm volatile("ldmatrix.sync.aligned.m8n8.x4.shared.b16 {%0,%1,%2,%3}, [%4];"
                 : "=r"(r[0]), "=r"(r[1]), "=r"(r[2]), "=r"(r[3]) : "r"(addr));
}
__device__ __forceinline__ void ldm4t(uint32_t* r, uint32_t addr) {
    asm volatile("ldmatrix.sync.aligned.m8n8.x4.trans.shared.b16 {%0,%1,%2,%3}, [%4];"
                 : "=r"(r[0]), "=r"(r[1]), "=r"(r[2]), "=r"(r[3]) : "r"(addr));
}
__device__ __forceinline__ void mma16816(float* c, const uint32_t* a,
                                         const uint32_t* b) {
    asm volatile(
        "mma.sync.aligned.m16n8k16.row.col.f32.bf16.bf16.f32 "
        "{%0,%1,%2,%3}, {%4,%5,%6,%7}, {%8,%9}, {%0,%1,%2,%3};"
        : "+f"(c[0]), "+f"(c[1]), "+f"(c[2]), "+f"(c[3])
        : "r"(a[0]), "r"(a[1]), "r"(a[2]), "r"(a[3]), "r"(b[0]), "r"(b[1]));
}
__device__ __forceinline__ uint32_t pack_hi(float x, float y) {
    __nv_bfloat162 h = __floats2bfloat162_rn(x, y);
    return *(uint32_t*)&h;
}

// ------------------------------------------------------------ split fp32 ----
__global__ void __launch_bounds__(256) split_kernel(
    const float* __restrict__ src, __nv_bfloat16* __restrict__ hi,
    __nv_bfloat16* __restrict__ lo, int n4)
{
    int i = blockIdx.x * blockDim.x + threadIdx.x;
    if (i >= n4) return;
    float4 a = ((const float4*)src)[i];
    __nv_bfloat16 h0 = __float2bfloat16(a.x);
    __nv_bfloat16 h1 = __float2bfloat16(a.y);
    __nv_bfloat16 h2 = __float2bfloat16(a.z);
    __nv_bfloat16 h3 = __float2bfloat16(a.w);
    __nv_bfloat16 l0 = __float2bfloat16(a.x - __bfloat162float(h0));
    __nv_bfloat16 l1 = __float2bfloat16(a.y - __bfloat162float(h1));
    __nv_bfloat16 l2 = __float2bfloat16(a.z - __bfloat162float(h2));
    __nv_bfloat16 l3 = __float2bfloat16(a.w - __bfloat162float(h3));
    ((__nv_bfloat162*)hi)[2*i]   = __nv_bfloat162(h0, h1);
    ((__nv_bfloat162*)hi)[2*i+1] = __nv_bfloat162(h2, h3);
    ((__nv_bfloat162*)lo)[2*i]   = __nv_bfloat162(l0, l1);
    ((__nv_bfloat162*)lo)[2*i+1] = __nv_bfloat162(l2, l3);
}

// --------------------------------------------------- mma.sync bf16 GEMM ----
// MODE 0: fp32 C[row][n]   MODE 1: bf16 hi/lo [B,H,L,HD]   MODE 2: MODE1+RoPE
#define SROWB 80
#define OPB   (128*SROWB)
#define STGB  (4*OPB)
#define GSTG  3
#define GSMEM (GSTG*STGB)

template<int MODE>
__global__ void __launch_bounds__(256) gemm_mma(
    const __nv_bfloat16* __restrict__ Ah, const __nv_bfloat16* __restrict__ Al,
    const __nv_bfloat16* __restrict__ Bh, const __nv_bfloat16* __restrict__ Bl,
    float* __restrict__ C,
    __nv_bfloat16* __restrict__ Ch, __nv_bfloat16* __restrict__ Cl,
    const float* __restrict__ cosc, const float* __restrict__ sinc)
{
    extern __shared__ char smem[];
    const uint32_t sb = smem_u32(smem);
    const int tid  = threadIdx.x;
    const int lane = tid & 31, wid = tid >> 5;
    const int wm = wid >> 2, wn = wid & 3;
    const int m0 = blockIdx.y * 128, n0 = blockIdx.x * 128;
    const int S = DM / 32;

    const int lrow = tid >> 1;
    const int lseg = (tid & 1) * 2;
    const size_t ga = (size_t)(m0 + lrow) * DM + lseg * 8;
    const size_t gb = (size_t)(n0 + lrow) * DM + lseg * 8;
    const uint32_t sd = lrow * SROWB + lseg * 16;

    float acc[4][4][4];
    #pragma unroll
    for (int i = 0; i < 4; ++i)
        #pragma unroll
        for (int j = 0; j < 4; ++j)
            #pragma unroll
            for (int q = 0; q < 4; ++q) acc[i][j][q] = 0.f;

    auto load_stage = [&](int s) {
        const int k0 = s * 32;
        const uint32_t base = sb + (s % GSTG) * STGB;
        const char* pah = (const char*)(Ah + ga + k0);
        const char* pal = (const char*)(Al + ga + k0);
        const char* pbh = (const char*)(Bh + gb + k0);
        const char* pbl = (const char*)(Bl + gb + k0);
        cp16(base +        sd,      pah);   cp16(base +        sd + 16, pah + 16);
        cp16(base + OPB  + sd,      pal);   cp16(base + OPB  + sd + 16, pal + 16);
        cp16(base + 2*OPB + sd,     pbh);   cp16(base + 2*OPB + sd + 16, pbh + 16);
        cp16(base + 3*OPB + sd,     pbl);   cp16(base + 3*OPB + sd + 16, pbl + 16);
        cp_commit();
    };

    load_stage(0);
    load_stage(1);

    const uint32_t a_off = (uint32_t)((wm*64 + (lane & 15)) * SROWB + (lane >> 4) * 16);
    const uint32_t b_off = (uint32_t)((wn*32 + ((lane >> 4) & 1)*8 + (lane & 7)) * SROWB
                                      + ((lane >> 3) & 1) * 16);

    for (int s = 0; s < S; ++s) {
        if (s == S - 1) cp_wait<0>(); else cp_wait<1>();
        __syncthreads();
        if (s + 2 < S) load_stage(s + 2);

        const uint32_t base = sb + (s % GSTG) * STGB;
        #pragma unroll
        for (int kk = 0; kk < 2; ++kk) {
            const uint32_t kadd = kk * 32;
            uint32_t ah[4][4], bh[2][4];
            #pragma unroll
            for (int i = 0; i < 4; ++i)
                ldm4(ah[i], base + a_off + i*16*SROWB + kadd);
            #pragma unroll
            for (int p = 0; p < 2; ++p)
                ldm4(bh[p], base + 2*OPB + b_off + p*16*SROWB + kadd);
            #pragma unroll
            for (int i = 0; i < 4; ++i)
                #pragma unroll
                for (int j = 0; j < 4; ++j)
                    mma16816(acc[i][j], ah[i], &bh[j >> 1][(j & 1) * 2]);
            {
                uint32_t al[4][4];
                #pragma unroll
                for (int i = 0; i < 4; ++i)
                    ldm4(al[i], base + OPB + a_off + i*16*SROWB + kadd);
                #pragma unroll
                for (int i = 0; i < 4; ++i)
                    #pragma unroll
                    for (int j = 0; j < 4; ++j)
                        mma16816(acc[i][j], al[i], &bh[j >> 1][(j & 1) * 2]);
            }
            {
                uint32_t bl[2][4];
                #pragma unroll
                for (int p = 0; p < 2; ++p)
                    ldm4(bl[p], base + 3*OPB + b_off + p*16*SROWB + kadd);
                #pragma unroll
                for (int i = 0; i < 4; ++i)
                    #pragma unroll
                    for (int j = 0; j < 4; ++j)
                        mma16816(acc[i][j], ah[i], &bl[j >> 1][(j & 1) * 2]);
            }
        }
    }

    // ---- epilogue via smem (stride 132 floats) ----
    __syncthreads();
    float* Cs = (float*)smem;
    const int frow = wm*64 + (lane >> 2);
    const int fcol = wn*32 + (lane & 3) * 2;
    #pragma unroll
    for (int i = 0; i < 4; ++i)
        #pragma unroll
        for (int j = 0; j < 4; ++j) {
            *(float2*)&Cs[(frow + i*16    )*132 + fcol + j*8] =
                make_float2(acc[i][j][0], acc[i][j][1]);
            *(float2*)&Cs[(frow + i*16 + 8)*132 + fcol + j*8] =
                make_float2(acc[i][j][2], acc[i][j][3]);
        }
    __syncthreads();

    const int row  = tid >> 1;
    const int half = tid & 1;
    const int grow = m0 + row;
    const int h = n0 >> 7;

    if (MODE == 0) {
        float* dst = C + (size_t)grow * DM + n0;
        #pragma unroll
        for (int c0 = 0; c0 < 32; c0 += 4) {
            const int col = half*32 + c0;
            *(float4*)(dst + col)      = *(float4*)&Cs[row*132 + col];
            *(float4*)(dst + col + 64) = *(float4*)&Cs[row*132 + col + 64];
        }
    } else {
        int bb = grow >> 11, l = grow & (LL - 1);
        size_t ofs = (((size_t)(bb * NH + h)) * LL + l) * HD;
        #pragma unroll
        for (int c0 = 0; c0 < 32; c0 += 4) {
            const int col = half*32 + c0;
            float a0[4], a1[4];
            #pragma unroll
            for (int q = 0; q < 4; ++q) {
                a0[q] = Cs[row*132 + col + q];
                a1[q] = Cs[row*132 + col + 64 + q];
            }
            if (MODE == 2) {
                #pragma unroll
                for (int q = 0; q < 4; ++q) {
                    float c1 = cosc[h*HD + col + q];
                    float s1 = sinc[h*HD + col + q];
                    float c2 = cosc[h*HD + col + q + 64];
                    float s2 = sinc[h*HD + col + q + 64];
                    float v0 = a0[q], v1 = a1[q];
                    a0[q] = v0*c1 - v1*s1;
                    a1[q] = v1*c2 + v0*s2;
                }
            }
            #pragma unroll
            for (int q = 0; q < 4; q += 2) {
                __nv_bfloat162 h0 = __floats2bfloat162_rn(a0[q], a0[q+1]);
                float2 f0 = __bfloat1622float2(h0);
                __nv_bfloat162 l0 = __floats2bfloat162_rn(a0[q]-f0.x, a0[q+1]-f0.y);
                *(__nv_bfloat162*)(Ch + ofs + col + q) = h0;
                *(__nv_bfloat162*)(Cl + ofs + col + q) = l0;
                __nv_bfloat162 h1 = __floats2bfloat162_rn(a1[q], a1[q+1]);
                float2 f1 = __bfloat1622float2(h1);
                __nv_bfloat162 l1 = __floats2bfloat162_rn(a1[q]-f1.x, a1[q+1]-f1.y);
                *(__nv_bfloat162*)(Ch + ofs + col + 64 + q) = h1;
                *(__nv_bfloat162*)(Cl + ofs + col + 64 + q) = l1;
            }
        }
    }
}

// ---------------------------------------------------- bf16 flash attention --
// q-tile 128, 8 warps (m16 each), key tiles of 64, double-buffered K/V.
// Unroll pressure kept LOW deliberately (ptxas compile-time guard).
#define APITCH 272
#define AT_QH 0
#define AT_QL 34816
#define AT_K  69632               /* + bs*34816 ; lo at +17408 */
#define AT_V  139264
#define AT_MASK 208896
#define AT_SMEM (208896 + 8192)   /* 217088 */

__global__ void __launch_bounds__(256) attn_mma(
    const __nv_bfloat16* __restrict__ Qh, const __nv_bfloat16* __restrict__ Ql,
    const __nv_bfloat16* __restrict__ Kh, const __nv_bfloat16* __restrict__ Kl,
    const __nv_bfloat16* __restrict__ Vh, const __nv_bfloat16* __restrict__ Vl,
    const int* __restrict__ mask,
    __nv_bfloat16* __restrict__ Oh, __nv_bfloat16* __restrict__ Ol)
{
    extern __shared__ char sm[];
    const uint32_t sb = smem_u32(sm);
    const int tid = threadIdx.x, lane = tid & 31, wid = tid >> 5;
    const int q0 = (int)(gridDim.x - 1 - blockIdx.x) * 128;   // heavy first
    const int h = blockIdx.y, b = blockIdx.z;
    const size_t hb = ((size_t)(b*NH + h)) * LL * HD;
    const __nv_bfloat16 *pQh = Qh+hb, *pQl = Ql+hb;
    const __nv_bfloat16 *pKh = Kh+hb, *pKl = Kl+hb;
    const __nv_bfloat16 *pVh = Vh+hb, *pVl = Vl+hb;
    int* msk = (int*)(sm + AT_MASK);

    for (int i = tid; i < LL; i += 256) msk[i] = mask[b*LL + i];

    // Q tile (128 rows x 128 hd, hi+lo)
    {
        int row = tid >> 1;
        const char* gqh = (const char*)(pQh + (size_t)(q0+row)*HD);
        const char* gql = (const char*)(pQl + (size_t)(q0+row)*HD);
        uint32_t dq = sb + row * APITCH;
        #pragma unroll
        for (int t = 0; t < 8; ++t) {
            int c = (tid & 1) + 2*t;
            cp16(dq + c*16,           gqh + c*16);
            cp16(dq + AT_QL + c*16,   gql + c*16);
        }
    }

    auto load_kv = [&](int kt, int bs) {
        int k0 = kt * 64;
        int row = tid >> 2;
        const char* gkh = (const char*)(pKh + (size_t)(k0+row)*HD);
        const char* gkl = (const char*)(pKl + (size_t)(k0+row)*HD);
        const char* gvh = (const char*)(pVh + (size_t)(k0+row)*HD);
        const char* gvl = (const char*)(pVl + (size_t)(k0+row)*HD);
        uint32_t dk = sb + AT_K + bs*34816 + row*APITCH;
        uint32_t dv = sb + AT_V + bs*34816 + row*APITCH;
        #pragma unroll
        for (int t = 0; t < 4; ++t) {
            int c = (tid & 3) + 4*t;
            cp16(dk + c*16,         gkh + c*16);
            cp16(dk + 17408 + c*16, gkl + c*16);
            cp16(dv + c*16,         gvh + c*16);
            cp16(dv + 17408 + c*16, gvl + c*16);
        }
        cp_commit();
    };

    const int ntiles = q0/64 + 2;
    load_kv(0, 0);            // group {Q, t0}
    load_kv(1, 1);            // group {t1}

    float oacc[16][4];
    #pragma unroll
    for (int u = 0; u < 16; ++u)
        #pragma unroll
        for (int q = 0; q < 4; ++q) oacc[u][q] = 0.f;
    float m_i[2] = {-1e30f, -1e30f}, l_i[2] = {0.f, 0.f};

    const uint32_t a_hi = sb + (wid*16 + (lane & 15))*APITCH + (lane >> 4)*16;
    const uint32_t a_lo = a_hi + AT_QL;
    const uint32_t b_off = (uint32_t)((((lane >> 4) & 1)*8 + (lane & 7))*APITCH
                                      + ((lane >> 3) & 1)*16);
    const uint32_t v_off = (uint32_t)((lane & 15)*APITCH + (lane >> 4)*16);
    const float scale = 0.08838834764831845f;   // 1/sqrt(128)
    const int r0 = lane >> 2;

    for (int kt = 0; kt < ntiles; ++kt) {
        const int bs = kt & 1;
        const int k0 = kt * 64;
        if (kt == ntiles - 1) cp_wait<0>(); else cp_wait<1>();
        __syncthreads();

        const uint32_t kh_base = sb + AT_K + bs*34816;
        const uint32_t vh_base = sb + AT_V + bs*34816;

        // ---- S = Q K^T (3-term) ----
        float sacc[8][4];
        #pragma unroll
        for (int j = 0; j < 8; ++j)
            #pragma unroll
            for (int q = 0; q < 4; ++q) sacc[j][q] = 0.f;

        #pragma unroll 2
        for (int ks = 0; ks < 8; ++ks) {
            const uint32_t ka = ks * 32;
            uint32_t ah[4], al[4], bh[4][4];
            ldm4(ah, a_hi + ka);
            ldm4(al, a_lo + ka);
            #pragma unroll
            for (int p = 0; p < 4; ++p)
                ldm4(bh[p], kh_base + b_off + p*16*APITCH + ka);
            #pragma unroll
            for (int j = 0; j < 8; ++j) {
                uint32_t* bb = &bh[j >> 1][(j & 1) * 2];
                mma16816(sacc[j], ah, bb);
                mma16816(sacc[j], al, bb);
            }
            uint32_t bl[4][4];
            #pragma unroll
            for (int p = 0; p < 4; ++p)
                ldm4(bl[p], kh_base + 17408 + b_off + p*16*APITCH + ka);
            #pragma unroll
            for (int j = 0; j < 8; ++j)
                mma16816(sacc[j], ah, &bl[j >> 1][(j & 1) * 2]);
        }

        // ---- online softmax (rows r0, r0+8 of this warp's m16) ----
        #pragma unroll
        for (int rr = 0; rr < 2; ++rr) {
            const int qr = q0 + wid*16 + r0 + rr*8;
            float tm = -1e30f;
            #pragma unroll
            for (int j = 0; j < 8; ++j) {
                #pragma unroll
                for (int e = 0; e < 2; ++e) {
                    int col = k0 + j*8 + (lane & 3)*2 + e;
                    float v = sacc[j][rr*2 + e] * scale;
                    if (col > qr || msk[col] == 0) v = -1e15f;
                    sacc[j][rr*2 + e] = v;
                    tm = fmaxf(tm, v);
                }
            }
            tm = fmaxf(tm, __shfl_xor_sync(0xffffffffu, tm, 1));
            tm = fmaxf(tm, __shfl_xor_sync(0xffffffffu, tm, 2));
            float mnew = fmaxf(m_i[rr], tm);
            float sc = __expf(m_i[rr] - mnew);
            m_i[rr] = mnew;
            float rs = 0.f;
            #pragma unroll
            for (int j = 0; j < 8; ++j) {
                #pragma unroll
                for (int e = 0; e < 2; ++e) {
                    float p = __expf(sacc[j][rr*2 + e] - mnew);
                    sacc[j][rr*2 + e] = p;
                    rs += p;
                }
            }
            rs += __shfl_xor_sync(0xffffffffu, rs, 1);
            rs += __shfl_xor_sync(0xffffffffu, rs, 2);
            l_i[rr] = l_i[rr] * sc + rs;
            #pragma unroll
            for (int u = 0; u < 16; ++u) {
                oacc[u][rr*2]     *= sc;
                oacc[u][rr*2 + 1] *= sc;
            }
        }

        // ---- O += P V (3-term; P split in-register) ----
        #pragma unroll 1
        for (int t = 0; t < 4; ++t) {
            uint32_t pah[4], pal[4];
            #pragma unroll
            for (int idx = 0; idx < 4; ++idx) {
                int j = 2*t + (idx >> 1);
                int o = (idx & 1) * 2;
                float p0 = sacc[j][o], p1 = sacc[j][o + 1];
                __nv_bfloat162 hv = __floats2bfloat162_rn(p0, p1);
                float2 hf = __bfloat1622float2(hv);
                pah[idx] = *(uint32_t*)&hv;
                pal[idx] = pack_hi(p0 - hf.x, p1 - hf.y);
            }
            #pragma unroll
            for (int u = 0; u < 8; ++u) {
                uint32_t vh[4], vl[4];
                uint32_t addr = vh_base + t*16*APITCH + u*32 + v_off;
                ldm4t(vh, addr);
                ldm4t(vl, addr + 17408);
                mma16816(oacc[2*u],     pah, vh);
                mma16816(oacc[2*u],     pal, vh);
                mma16816(oacc[2*u],     pah, vl);
                mma16816(oacc[2*u + 1], pah, vh + 2);
                mma16816(oacc[2*u + 1], pal, vh + 2);
                mma16816(oacc[2*u + 1], pah, vl + 2);
            }
        }

        if (kt + 2 < ntiles) {
            __syncthreads();
            load_kv(kt + 2, bs);
        }
    }

    // ---- epilogue: bf16 hi/lo to [B, L, DM] (O-proj A operand) ----
    #pragma unroll
    for (int rr = 0; rr < 2; ++rr) {
        float inv = 1.0f / l_i[rr];
        int lrow = q0 + wid*16 + r0 + rr*8;
        size_t base = ((size_t)(b*LL + lrow)) * DM + h*HD;
        #pragma unroll
        for (int u = 0; u < 16; ++u) {
            int col = u*8 + (lane & 3)*2;
            float p0 = oacc[u][rr*2]     * inv;
            float p1 = oacc[u][rr*2 + 1] * inv;
            __nv_bfloat162 hv = __floats2bfloat162_rn(p0, p1);
            float2 hf = __bfloat1622float2(hv);
            __nv_bfloat162 lv = __floats2bfloat162_rn(p0 - hf.x, p1 - hf.y);
            *(__nv_bfloat162*)(Oh + base + col) = hv;
            *(__nv_bfloat162*)(Ol + base + col) = lv;
        }
    }
}

// ---------------------------------------------------------------------------
extern "C" void kernel_launch(void* const* d_in, const int* in_sizes, int n_in,
                              void* d_out, int out_size)
{
    const float* hidden = (const float*)d_in[0];
    const int*   mask   = (const int*)  d_in[1];
    const float* Wq     = (const float*)d_in[2];
    const float* Wk     = (const float*)d_in[3];
    const float* Wv     = (const float*)d_in[4];
    const float* Wo     = (const float*)d_in[5];
    const float* cosc   = (const float*)d_in[6];
    const float* sinc   = (const float*)d_in[7];
    float* out = (float*)d_out;

    __nv_bfloat16 *Ahp, *Alp, *Whp, *Wlp, *Qhp, *Qlp, *Khp, *Klp, *Vhp, *Vlp;
    cudaGetSymbolAddress((void**)&Ahp, g_Ah);
    cudaGetSymbolAddress((void**)&Alp, g_Al);
    cudaGetSymbolAddress((void**)&Whp, g_Wh);
    cudaGetSymbolAddress((void**)&Wlp, g_Wl);
    cudaGetSymbolAddress((void**)&Qhp, g_Qh);
    cudaGetSymbolAddress((void**)&Qlp, g_Ql);
    cudaGetSymbolAddress((void**)&Khp, g_Kh);
    cudaGetSymbolAddress((void**)&Klp, g_Kl);
    cudaGetSymbolAddress((void**)&Vhp, g_Vh);
    cudaGetSymbolAddress((void**)&Vlp, g_Vl);

    cudaFuncSetAttribute(gemm_mma<0>, cudaFuncAttributeMaxDynamicSharedMemorySize, GSMEM);
    cudaFuncSetAttribute(gemm_mma<1>, cudaFuncAttributeMaxDynamicSharedMemorySize, GSMEM);
    cudaFuncSetAttribute(gemm_mma<2>, cudaFuncAttributeMaxDynamicSharedMemorySize, GSMEM);
    cudaFuncSetAttribute(attn_mma,    cudaFuncAttributeMaxDynamicSharedMemorySize, AT_SMEM);

    const int nA4 = MROWS*DM/4, nW4 = DM*DM/4;
    dim3 gg(DM/128, MROWS/128);

    split_kernel<<<(nA4+255)/256, 256>>>(hidden, Ahp, Alp, nA4);

    split_kernel<<<(nW4+255)/256, 256>>>(Wq, Whp, Wlp, nW4);
    gemm_mma<2><<<gg, 256, GSMEM>>>(Ahp, Alp, Whp, Wlp, nullptr, Qhp, Qlp, cosc, sinc);

    split_kernel<<<(nW4+255)/256, 256>>>(Wk, Whp, Wlp, nW4);
    gemm_mma<2><<<gg, 256, GSMEM>>>(Ahp, Alp, Whp, Wlp, nullptr, Khp, Klp, cosc, sinc);

    split_kernel<<<(nW4+255)/256, 256>>>(Wv, Whp, Wlp, nW4);
    gemm_mma<1><<<gg, 256, GSMEM>>>(Ahp, Alp, Whp, Wlp, nullptr, Vhp, Vlp, nullptr, nullptr);

    dim3 ga(LL/128, NH, BB);
    attn_mma<<<ga, 256, AT_SMEM>>>(Qhp, Qlp, Khp, Klp, Vhp, Vlp, mask, Ahp, Alp);

    split_kernel<<<(nW4+255)/256, 256>>>(Wo, Whp, Wlp, nW4);
    gemm_mma<0><<<gg, 256, GSMEM>>>(Ahp, Alp, Whp, Wlp, out, nullptr, nullptr, nullptr, nullptr);
}

// round 8
// speedup vs baseline: 2.4815x; 1.1332x over previous
#include <cuda_runtime.h>
#include <cuda_bf16.h>
#include <cstdint>
#include <math.h>

#define BB 2
#define LL 2048
#define DM 2048
#define NH 16
#define HD 128
#define MROWS (BB*LL)   // 4096

// ---------------------------------------------------------------- scratch ---
__device__ __nv_bfloat16 g_Ah[MROWS*DM];
__device__ __nv_bfloat16 g_Al[MROWS*DM];
__device__ __nv_bfloat16 g_Wh[DM*DM];
__device__ __nv_bfloat16 g_Wl[DM*DM];
__device__ __nv_bfloat16 g_Qh[MROWS*DM];
__device__ __nv_bfloat16 g_Ql[MROWS*DM];
__device__ __nv_bfloat16 g_Kh[MROWS*DM];
__device__ __nv_bfloat16 g_Kl[MROWS*DM];
__device__ __nv_bfloat16 g_Vh[MROWS*DM];
__device__ __nv_bfloat16 g_Vl[MROWS*DM];

// ------------------------------------------------------------ ptx helpers ---
__device__ __forceinline__ uint32_t smem_u32(const void* p) {
    uint32_t a;
    asm("{ .reg .u64 t; cvta.to.shared.u64 t, %1; cvt.u32.u64 %0, t; }"
        : "=r"(a) : "l"(p));
    return a;
}
__device__ __forceinline__ void cp16(uint32_t d, const void* s) {
    asm volatile("cp.async.cg.shared.global [%0], [%1], 16;" :: "r"(d), "l"(s));
}
__device__ __forceinline__ void cp_commit() {
    asm volatile("cp.async.commit_group;" ::: "memory");
}
template<int N> __device__ __forceinline__ void cp_wait() {
    asm volatile("cp.async.wait_group %0;" :: "n"(N) : "memory");
}
__device__ __forceinline__ void ldm4(uint32_t* r, uint32_t addr) {
    asm volatile("ldmatrix.sync.aligned.m8n8.x4.shared.b16 {%0,%1,%2,%3}, [%4];"
                 : "=r"(r[0]), "=r"(r[1]), "=r"(r[2]), "=r"(r[3]) : "r"(addr));
}
__device__ __forceinline__ void ldm4t(uint32_t* r, uint32_t addr) {
    asm volatile("ldmatrix.sync.aligned.m8n8.x4.trans.shared.b16 {%0,%1,%2,%3}, [%4];"
                 : "=r"(r[0]), "=r"(r[1]), "=r"(r[2]), "=r"(r[3]) : "r"(addr));
}
__device__ __forceinline__ void mma16816(float* c, const uint32_t* a,
                                         const uint32_t* b) {
    asm volatile(
        "mma.sync.aligned.m16n8k16.row.col.f32.bf16.bf16.f32 "
        "{%0,%1,%2,%3}, {%4,%5,%6,%7}, {%8,%9}, {%0,%1,%2,%3};"
        : "+f"(c[0]), "+f"(c[1]), "+f"(c[2]), "+f"(c[3])
        : "r"(a[0]), "r"(a[1]), "r"(a[2]), "r"(a[3]), "r"(b[0]), "r"(b[1]));
}
__device__ __forceinline__ uint32_t pack_hi(float x, float y) {
    __nv_bfloat162 h = __floats2bfloat162_rn(x, y);
    return *(uint32_t*)&h;
}

// ------------------------------------------------------------ split fp32 ----
__global__ void __launch_bounds__(256) split_kernel(
    const float* __restrict__ src, __nv_bfloat16* __restrict__ hi,
    __nv_bfloat16* __restrict__ lo, int n4)
{
    int i = blockIdx.x * blockDim.x + threadIdx.x;
    if (i >= n4) return;
    float4 a = ((const float4*)src)[i];
    __nv_bfloat16 h0 = __float2bfloat16(a.x);
    __nv_bfloat16 h1 = __float2bfloat16(a.y);
    __nv_bfloat16 h2 = __float2bfloat16(a.z);
    __nv_bfloat16 h3 = __float2bfloat16(a.w);
    __nv_bfloat16 l0 = __float2bfloat16(a.x - __bfloat162float(h0));
    __nv_bfloat16 l1 = __float2bfloat16(a.y - __bfloat162float(h1));
    __nv_bfloat16 l2 = __float2bfloat16(a.z - __bfloat162float(h2));
    __nv_bfloat16 l3 = __float2bfloat16(a.w - __bfloat162float(h3));
    ((__nv_bfloat162*)hi)[2*i]   = __nv_bfloat162(h0, h1);
    ((__nv_bfloat162*)hi)[2*i+1] = __nv_bfloat162(h2, h3);
    ((__nv_bfloat162*)lo)[2*i]   = __nv_bfloat162(l0, l1);
    ((__nv_bfloat162*)lo)[2*i+1] = __nv_bfloat162(l2, l3);
}

// --------------------------------------------------- mma.sync bf16 GEMM ----
// Rows packed [hi(64B)|lo(64B)] = 128B, SW128 XOR swizzle (chunk ^= row&7).
// Stage = A(16KB) + B(16KB) = 32KB; 3 stages = 96KB -> 2 CTAs/SM.
// MODE 0: fp32 C[row][n]   MODE 1: bf16 hi/lo [B,H,L,HD]   MODE 2: MODE1+RoPE
#define AREG  16384
#define STGB  32768
#define GSTG  3
#define GSMEM (GSTG*STGB)     /* 98304 */

template<int MODE>
__global__ void __launch_bounds__(256, 2) gemm_mma(
    const __nv_bfloat16* __restrict__ Ah, const __nv_bfloat16* __restrict__ Al,
    const __nv_bfloat16* __restrict__ Bh, const __nv_bfloat16* __restrict__ Bl,
    float* __restrict__ C,
    __nv_bfloat16* __restrict__ Ch, __nv_bfloat16* __restrict__ Cl,
    const float* __restrict__ cosc, const float* __restrict__ sinc)
{
    extern __shared__ char smem[];
    const uint32_t sb = smem_u32(smem);
    const int tid  = threadIdx.x;
    const int lane = tid & 31, wid = tid >> 5;
    const int wm = wid >> 2, wn = wid & 3;
    const int m0 = blockIdx.y * 128, n0 = blockIdx.x * 128;
    const int S = DM / 32;

    // loader: thread handles row r = tid>>1, chunk pair (tid&1)
    const int lr = tid >> 1;
    const uint32_t lsx = (uint32_t)(lr & 7) << 4;
    const int lj0 = (tid & 1) * 2;
    const size_t ga = (size_t)(m0 + lr) * DM;
    const size_t gb = (size_t)(n0 + lr) * DM;

    float acc[4][4][4];
    #pragma unroll
    for (int i = 0; i < 4; ++i)
        #pragma unroll
        for (int j = 0; j < 4; ++j)
            #pragma unroll
            for (int q = 0; q < 4; ++q) acc[i][j][q] = 0.f;

    auto load_stage = [&](int s) {
        const int k0 = s * 32;
        const uint32_t ab = sb + (s % GSTG) * STGB + (uint32_t)lr * 128;
        const uint32_t bb = ab + AREG;
        const char* pah = (const char*)(Ah + ga + k0);
        const char* pal = (const char*)(Al + ga + k0);
        const char* pbh = (const char*)(Bh + gb + k0);
        const char* pbl = (const char*)(Bl + gb + k0);
        #pragma unroll
        for (int q = 0; q < 2; ++q) {
            const int j = lj0 + q;
            cp16(ab + (((uint32_t)(j    ) << 4) ^ lsx), pah + j*16);
            cp16(ab + (((uint32_t)(j + 4) << 4) ^ lsx), pal + j*16);
            cp16(bb + (((uint32_t)(j    ) << 4) ^ lsx), pbh + j*16);
            cp16(bb + (((uint32_t)(j + 4) << 4) ^ lsx), pbl + j*16);
        }
        cp_commit();
    };

    load_stage(0);
    load_stage(1);

    // reader offsets
    const uint32_t sx = (uint32_t)(lane & 7) << 4;
    const uint32_t a_row = (uint32_t)(wm*64 + (lane & 15)) * 128;
    const uint32_t a_k   = (uint32_t)(lane >> 4) << 4;            // 0 / 16
    const uint32_t b_row = (uint32_t)(wn*32 + ((lane >> 4) & 1)*8 + (lane & 7)) * 128;
    const uint32_t b_k   = (uint32_t)((lane >> 3) & 1) << 4;      // 0 / 16

    for (int s = 0; s < S; ++s) {
        if (s == S - 1) cp_wait<0>(); else cp_wait<1>();
        __syncthreads();
        if (s + 2 < S) load_stage(s + 2);

        const uint32_t Abase = sb + (s % GSTG) * STGB;
        const uint32_t Bbase = Abase + AREG;
        #pragma unroll
        for (int kk = 0; kk < 2; ++kk) {
            const uint32_t kb = (uint32_t)kk * 32;
            uint32_t ah[4][4], bh[2][4];
            #pragma unroll
            for (int i = 0; i < 4; ++i)
                ldm4(ah[i], Abase + a_row + i*2048 + ((kb + a_k) ^ sx));
            #pragma unroll
            for (int p = 0; p < 2; ++p)
                ldm4(bh[p], Bbase + b_row + p*2048 + ((kb + b_k) ^ sx));
            #pragma unroll
            for (int i = 0; i < 4; ++i)
                #pragma unroll
                for (int j = 0; j < 4; ++j)
                    mma16816(acc[i][j], ah[i], &bh[j >> 1][(j & 1) * 2]);
            {
                uint32_t al[4][4];
                #pragma unroll
                for (int i = 0; i < 4; ++i)
                    ldm4(al[i], Abase + a_row + i*2048 + ((64 + kb + a_k) ^ sx));
                #pragma unroll
                for (int i = 0; i < 4; ++i)
                    #pragma unroll
                    for (int j = 0; j < 4; ++j)
                        mma16816(acc[i][j], al[i], &bh[j >> 1][(j & 1) * 2]);
            }
            {
                uint32_t bl[2][4];
                #pragma unroll
                for (int p = 0; p < 2; ++p)
                    ldm4(bl[p], Bbase + b_row + p*2048 + ((64 + kb + b_k) ^ sx));
                #pragma unroll
                for (int i = 0; i < 4; ++i)
                    #pragma unroll
                    for (int j = 0; j < 4; ++j)
                        mma16816(acc[i][j], ah[i], &bl[j >> 1][(j & 1) * 2]);
            }
        }
    }

    // ---- epilogue via smem (stride 132 floats; 67584B < GSMEM) ----
    __syncthreads();
    float* Cs = (float*)smem;
    const int frow = wm*64 + (lane >> 2);
    const int fcol = wn*32 + (lane & 3) * 2;
    #pragma unroll
    for (int i = 0; i < 4; ++i)
        #pragma unroll
        for (int j = 0; j < 4; ++j) {
            *(float2*)&Cs[(frow + i*16    )*132 + fcol + j*8] =
                make_float2(acc[i][j][0], acc[i][j][1]);
            *(float2*)&Cs[(frow + i*16 + 8)*132 + fcol + j*8] =
                make_float2(acc[i][j][2], acc[i][j][3]);
        }
    __syncthreads();

    const int row  = tid >> 1;
    const int half = tid & 1;
    const int grow = m0 + row;
    const int h = n0 >> 7;

    if (MODE == 0) {
        float* dst = C + (size_t)grow * DM + n0;
        #pragma unroll
        for (int c0 = 0; c0 < 32; c0 += 4) {
            const int col = half*32 + c0;
            *(float4*)(dst + col)      = *(float4*)&Cs[row*132 + col];
            *(float4*)(dst + col + 64) = *(float4*)&Cs[row*132 + col + 64];
        }
    } else {
        int bb = grow >> 11, l = grow & (LL - 1);
        size_t ofs = (((size_t)(bb * NH + h)) * LL + l) * HD;
        #pragma unroll
        for (int c0 = 0; c0 < 32; c0 += 4) {
            const int col = half*32 + c0;
            float a0[4], a1[4];
            #pragma unroll
            for (int q = 0; q < 4; ++q) {
                a0[q] = Cs[row*132 + col + q];
                a1[q] = Cs[row*132 + col + 64 + q];
            }
            if (MODE == 2) {
                #pragma unroll
                for (int q = 0; q < 4; ++q) {
                    float c1 = cosc[h*HD + col + q];
                    float s1 = sinc[h*HD + col + q];
                    float c2 = cosc[h*HD + col + q + 64];
                    float s2 = sinc[h*HD + col + q + 64];
                    float v0 = a0[q], v1 = a1[q];
                    a0[q] = v0*c1 - v1*s1;
                    a1[q] = v1*c2 + v0*s2;
                }
            }
            #pragma unroll
            for (int q = 0; q < 4; q += 2) {
                __nv_bfloat162 h0 = __floats2bfloat162_rn(a0[q], a0[q+1]);
                float2 f0 = __bfloat1622float2(h0);
                __nv_bfloat162 l0 = __floats2bfloat162_rn(a0[q]-f0.x, a0[q+1]-f0.y);
                *(__nv_bfloat162*)(Ch + ofs + col + q) = h0;
                *(__nv_bfloat162*)(Cl + ofs + col + q) = l0;
                __nv_bfloat162 h1 = __floats2bfloat162_rn(a1[q], a1[q+1]);
                float2 f1 = __bfloat1622float2(h1);
                __nv_bfloat162 l1 = __floats2bfloat162_rn(a1[q]-f1.x, a1[q+1]-f1.y);
                *(__nv_bfloat162*)(Ch + ofs + col + 64 + q) = h1;
                *(__nv_bfloat162*)(Cl + ofs + col + 64 + q) = l1;
            }
        }
    }
}

// ---------------------------------------------------- bf16 flash attention --
// q-tile 128, 8 warps (m16 each), key tiles of 64, double-buffered K/V.
// Unroll pressure kept LOW deliberately (ptxas compile-time guard).
#define APITCH 272
#define AT_QH 0
#define AT_QL 34816
#define AT_K  69632               /* + bs*34816 ; lo at +17408 */
#define AT_V  139264
#define AT_MASK 208896
#define AT_SMEM (208896 + 8192)   /* 217088 */

__global__ void __launch_bounds__(256) attn_mma(
    const __nv_bfloat16* __restrict__ Qh, const __nv_bfloat16* __restrict__ Ql,
    const __nv_bfloat16* __restrict__ Kh, const __nv_bfloat16* __restrict__ Kl,
    const __nv_bfloat16* __restrict__ Vh, const __nv_bfloat16* __restrict__ Vl,
    const int* __restrict__ mask,
    __nv_bfloat16* __restrict__ Oh, __nv_bfloat16* __restrict__ Ol)
{
    extern __shared__ char sm[];
    const uint32_t sb = smem_u32(sm);
    const int tid = threadIdx.x, lane = tid & 31, wid = tid >> 5;
    const int q0 = (int)(gridDim.x - 1 - blockIdx.x) * 128;   // heavy first
    const int h = blockIdx.y, b = blockIdx.z;
    const size_t hb = ((size_t)(b*NH + h)) * LL * HD;
    const __nv_bfloat16 *pQh = Qh+hb, *pQl = Ql+hb;
    const __nv_bfloat16 *pKh = Kh+hb, *pKl = Kl+hb;
    const __nv_bfloat16 *pVh = Vh+hb, *pVl = Vl+hb;
    int* msk = (int*)(sm + AT_MASK);

    for (int i = tid; i < LL; i += 256) msk[i] = mask[b*LL + i];

    // Q tile (128 rows x 128 hd, hi+lo)
    {
        int row = tid >> 1;
        const char* gqh = (const char*)(pQh + (size_t)(q0+row)*HD);
        const char* gql = (const char*)(pQl + (size_t)(q0+row)*HD);
        uint32_t dq = sb + row * APITCH;
        #pragma unroll
        for (int t = 0; t < 8; ++t) {
            int c = (tid & 1) + 2*t;
            cp16(dq + c*16,           gqh + c*16);
            cp16(dq + AT_QL + c*16,   gql + c*16);
        }
    }

    auto load_kv = [&](int kt, int bs) {
        int k0 = kt * 64;
        int row = tid >> 2;
        const char* gkh = (const char*)(pKh + (size_t)(k0+row)*HD);
        const char* gkl = (const char*)(pKl + (size_t)(k0+row)*HD);
        const char* gvh = (const char*)(pVh + (size_t)(k0+row)*HD);
        const char* gvl = (const char*)(pVl + (size_t)(k0+row)*HD);
        uint32_t dk = sb + AT_K + bs*34816 + row*APITCH;
        uint32_t dv = sb + AT_V + bs*34816 + row*APITCH;
        #pragma unroll
        for (int t = 0; t < 4; ++t) {
            int c = (tid & 3) + 4*t;
            cp16(dk + c*16,         gkh + c*16);
            cp16(dk + 17408 + c*16, gkl + c*16);
            cp16(dv + c*16,         gvh + c*16);
            cp16(dv + 17408 + c*16, gvl + c*16);
        }
        cp_commit();
    };

    const int ntiles = q0/64 + 2;
    load_kv(0, 0);            // group {Q, t0}
    load_kv(1, 1);            // group {t1}

    float oacc[16][4];
    #pragma unroll
    for (int u = 0; u < 16; ++u)
        #pragma unroll
        for (int q = 0; q < 4; ++q) oacc[u][q] = 0.f;
    float m_i[2] = {-1e30f, -1e30f}, l_i[2] = {0.f, 0.f};

    const uint32_t a_hi = sb + (wid*16 + (lane & 15))*APITCH + (lane >> 4)*16;
    const uint32_t a_lo = a_hi + AT_QL;
    const uint32_t b_off = (uint32_t)((((lane >> 4) & 1)*8 + (lane & 7))*APITCH
                                      + ((lane >> 3) & 1)*16);
    const uint32_t v_off = (uint32_t)((lane & 15)*APITCH + (lane >> 4)*16);
    const float scale = 0.08838834764831845f;   // 1/sqrt(128)
    const int r0 = lane >> 2;

    for (int kt = 0; kt < ntiles; ++kt) {
        const int bs = kt & 1;
        const int k0 = kt * 64;
        if (kt == ntiles - 1) cp_wait<0>(); else cp_wait<1>();
        __syncthreads();

        const uint32_t kh_base = sb + AT_K + bs*34816;
        const uint32_t vh_base = sb + AT_V + bs*34816;

        // ---- S = Q K^T (3-term) ----
        float sacc[8][4];
        #pragma unroll
        for (int j = 0; j < 8; ++j)
            #pragma unroll
            for (int q = 0; q < 4; ++q) sacc[j][q] = 0.f;

        #pragma unroll 2
        for (int ks = 0; ks < 8; ++ks) {
            const uint32_t ka = ks * 32;
            uint32_t ah[4], al[4], bh[4][4];
            ldm4(ah, a_hi + ka);
            ldm4(al, a_lo + ka);
            #pragma unroll
            for (int p = 0; p < 4; ++p)
                ldm4(bh[p], kh_base + b_off + p*16*APITCH + ka);
            #pragma unroll
            for (int j = 0; j < 8; ++j) {
                uint32_t* bb = &bh[j >> 1][(j & 1) * 2];
                mma16816(sacc[j], ah, bb);
                mma16816(sacc[j], al, bb);
            }
            uint32_t bl[4][4];
            #pragma unroll
            for (int p = 0; p < 4; ++p)
                ldm4(bl[p], kh_base + 17408 + b_off + p*16*APITCH + ka);
            #pragma unroll
            for (int j = 0; j < 8; ++j)
                mma16816(sacc[j], ah, &bl[j >> 1][(j & 1) * 2]);
        }

        // ---- online softmax (rows r0, r0+8 of this warp's m16) ----
        #pragma unroll
        for (int rr = 0; rr < 2; ++rr) {
            const int qr = q0 + wid*16 + r0 + rr*8;
            float tm = -1e30f;
            #pragma unroll
            for (int j = 0; j < 8; ++j) {
                #pragma unroll
                for (int e = 0; e < 2; ++e) {
                    int col = k0 + j*8 + (lane & 3)*2 + e;
                    float v = sacc[j][rr*2 + e] * scale;
                    if (col > qr || msk[col] == 0) v = -1e15f;
                    sacc[j][rr*2 + e] = v;
                    tm = fmaxf(tm, v);
                }
            }
            tm = fmaxf(tm, __shfl_xor_sync(0xffffffffu, tm, 1));
            tm = fmaxf(tm, __shfl_xor_sync(0xffffffffu, tm, 2));
            float mnew = fmaxf(m_i[rr], tm);
            float sc = __expf(m_i[rr] - mnew);
            m_i[rr] = mnew;
            float rs = 0.f;
            #pragma unroll
            for (int j = 0; j < 8; ++j) {
                #pragma unroll
                for (int e = 0; e < 2; ++e) {
                    float p = __expf(sacc[j][rr*2 + e] - mnew);
                    sacc[j][rr*2 + e] = p;
                    rs += p;
                }
            }
            rs += __shfl_xor_sync(0xffffffffu, rs, 1);
            rs += __shfl_xor_sync(0xffffffffu, rs, 2);
            l_i[rr] = l_i[rr] * sc + rs;
            #pragma unroll
            for (int u = 0; u < 16; ++u) {
                oacc[u][rr*2]     *= sc;
                oacc[u][rr*2 + 1] *= sc;
            }
        }

        // ---- O += P V (3-term; P split in-register) ----
        #pragma unroll 1
        for (int t = 0; t < 4; ++t) {
            uint32_t pah[4], pal[4];
            #pragma unroll
            for (int idx = 0; idx < 4; ++idx) {
                int j = 2*t + (idx >> 1);
                int o = (idx & 1) * 2;
                float p0 = sacc[j][o], p1 = sacc[j][o + 1];
                __nv_bfloat162 hv = __floats2bfloat162_rn(p0, p1);
                float2 hf = __bfloat1622float2(hv);
                pah[idx] = *(uint32_t*)&hv;
                pal[idx] = pack_hi(p0 - hf.x, p1 - hf.y);
            }
            #pragma unroll
            for (int u = 0; u < 8; ++u) {
                uint32_t vh[4], vl[4];
                uint32_t addr = vh_base + t*16*APITCH + u*32 + v_off;
                ldm4t(vh, addr);
                ldm4t(vl, addr + 17408);
                mma16816(oacc[2*u],     pah, vh);
                mma16816(oacc[2*u],     pal, vh);
                mma16816(oacc[2*u],     pah, vl);
                mma16816(oacc[2*u + 1], pah, vh + 2);
                mma16816(oacc[2*u + 1], pal, vh + 2);
                mma16816(oacc[2*u + 1], pah, vl + 2);
            }
        }

        if (kt + 2 < ntiles) {
            __syncthreads();
            load_kv(kt + 2, bs);
        }
    }

    // ---- epilogue: bf16 hi/lo to [B, L, DM] (O-proj A operand) ----
    #pragma unroll
    for (int rr = 0; rr < 2; ++rr) {
        float inv = 1.0f / l_i[rr];
        int lrow = q0 + wid*16 + r0 + rr*8;
        size_t base = ((size_t)(b*LL + lrow)) * DM + h*HD;
        #pragma unroll
        for (int u = 0; u < 16; ++u) {
            int col = u*8 + (lane & 3)*2;
            float p0 = oacc[u][rr*2]     * inv;
            float p1 = oacc[u][rr*2 + 1] * inv;
            __nv_bfloat162 hv = __floats2bfloat162_rn(p0, p1);
            float2 hf = __bfloat1622float2(hv);
            __nv_bfloat162 lv = __floats2bfloat162_rn(p0 - hf.x, p1 - hf.y);
            *(__nv_bfloat162*)(Oh + base + col) = hv;
            *(__nv_bfloat162*)(Ol + base + col) = lv;
        }
    }
}

// ---------------------------------------------------------------------------
extern "C" void kernel_launch(void* const* d_in, const int* in_sizes, int n_in,
                              void* d_out, int out_size)
{
    const float* hidden = (const float*)d_in[0];
    const int*   mask   = (const int*)  d_in[1];
    const float* Wq     = (const float*)d_in[2];
    const float* Wk     = (const float*)d_in[3];
    const float* Wv     = (const float*)d_in[4];
    const float* Wo     = (const float*)d_in[5];
    const float* cosc   = (const float*)d_in[6];
    const float* sinc   = (const float*)d_in[7];
    float* out = (float*)d_out;

    __nv_bfloat16 *Ahp, *Alp, *Whp, *Wlp, *Qhp, *Qlp, *Khp, *Klp, *Vhp, *Vlp;
    cudaGetSymbolAddress((void**)&Ahp, g_Ah);
    cudaGetSymbolAddress((void**)&Alp, g_Al);
    cudaGetSymbolAddress((void**)&Whp, g_Wh);
    cudaGetSymbolAddress((void**)&Wlp, g_Wl);
    cudaGetSymbolAddress((void**)&Qhp, g_Qh);
    cudaGetSymbolAddress((void**)&Qlp, g_Ql);
    cudaGetSymbolAddress((void**)&Khp, g_Kh);
    cudaGetSymbolAddress((void**)&Klp, g_Kl);
    cudaGetSymbolAddress((void**)&Vhp, g_Vh);
    cudaGetSymbolAddress((void**)&Vlp, g_Vl);

    cudaFuncSetAttribute(gemm_mma<0>, cudaFuncAttributeMaxDynamicSharedMemorySize, GSMEM);
    cudaFuncSetAttribute(gemm_mma<1>, cudaFuncAttributeMaxDynamicSharedMemorySize, GSMEM);
    cudaFuncSetAttribute(gemm_mma<2>, cudaFuncAttributeMaxDynamicSharedMemorySize, GSMEM);
    cudaFuncSetAttribute(attn_mma,    cudaFuncAttributeMaxDynamicSharedMemorySize, AT_SMEM);

    const int nA4 = MROWS*DM/4, nW4 = DM*DM/4;
    dim3 gg(DM/128, MROWS/128);

    split_kernel<<<(nA4+255)/256, 256>>>(hidden, Ahp, Alp, nA4);

    split_kernel<<<(nW4+255)/256, 256>>>(Wq, Whp, Wlp, nW4);
    gemm_mma<2><<<gg, 256, GSMEM>>>(Ahp, Alp, Whp, Wlp, nullptr, Qhp, Qlp, cosc, sinc);

    split_kernel<<<(nW4+255)/256, 256>>>(Wk, Whp, Wlp, nW4);
    gemm_mma<2><<<gg, 256, GSMEM>>>(Ahp, Alp, Whp, Wlp, nullptr, Khp, Klp, cosc, sinc);

    split_kernel<<<(nW4+255)/256, 256>>>(Wv, Whp, Wlp, nW4);
    gemm_mma<1><<<gg, 256, GSMEM>>>(Ahp, Alp, Whp, Wlp, nullptr, Vhp, Vlp, nullptr, nullptr);

    dim3 ga(LL/128, NH, BB);
    attn_mma<<<ga, 256, AT_SMEM>>>(Qhp, Qlp, Khp, Klp, Vhp, Vlp, mask, Ahp, Alp);

    split_kernel<<<(nW4+255)/256, 256>>>(Wo, Whp, Wlp, nW4);
    gemm_mma<0><<<gg, 256, GSMEM>>>(Ahp, Alp, Whp, Wlp, out, nullptr, nullptr, nullptr, nullptr);
}

// round 10
// speedup vs baseline: 2.6575x; 1.0709x over previous
#include <cuda_runtime.h>
#include <cuda_bf16.h>
#include <cstdint>
#include <math.h>

#define BB 2
#define LL 2048
#define DM 2048
#define NH 16
#define HD 128
#define MROWS (BB*LL)   // 4096
#define WSZ ((size_t)DM*(size_t)DM)

// ---------------------------------------------------------------- scratch ---
__device__ __nv_bfloat16 g_Ah[MROWS*DM];
__device__ __nv_bfloat16 g_Al[MROWS*DM];
__device__ __nv_bfloat16 g_W4h[4*DM*DM];
__device__ __nv_bfloat16 g_W4l[4*DM*DM];
__device__ __nv_bfloat16 g_Qh[MROWS*DM];
__device__ __nv_bfloat16 g_Ql[MROWS*DM];
__device__ __nv_bfloat16 g_Kh[MROWS*DM];
__device__ __nv_bfloat16 g_Kl[MROWS*DM];
__device__ __nv_bfloat16 g_Vh[MROWS*DM];
__device__ __nv_bfloat16 g_Vl[MROWS*DM];

// ------------------------------------------------------------ ptx helpers ---
__device__ __forceinline__ uint32_t smem_u32(const void* p) {
    uint32_t a;
    asm("{ .reg .u64 t; cvta.to.shared.u64 t, %1; cvt.u32.u64 %0, t; }"
        : "=r"(a) : "l"(p));
    return a;
}
__device__ __forceinline__ void cp16(uint32_t d, const void* s) {
    asm volatile("cp.async.cg.shared.global [%0], [%1], 16;" :: "r"(d), "l"(s));
}
__device__ __forceinline__ void cp_commit() {
    asm volatile("cp.async.commit_group;" ::: "memory");
}
template<int N> __device__ __forceinline__ void cp_wait() {
    asm volatile("cp.async.wait_group %0;" :: "n"(N) : "memory");
}
__device__ __forceinline__ void ldm4(uint32_t* r, uint32_t addr) {
    asm volatile("ldmatrix.sync.aligned.m8n8.x4.shared.b16 {%0,%1,%2,%3}, [%4];"
                 : "=r"(r[0]), "=r"(r[1]), "=r"(r[2]), "=r"(r[3]) : "r"(addr));
}
__device__ __forceinline__ void ldm4t(uint32_t* r, uint32_t addr) {
    asm volatile("ldmatrix.sync.aligned.m8n8.x4.trans.shared.b16 {%0,%1,%2,%3}, [%4];"
                 : "=r"(r[0]), "=r"(r[1]), "=r"(r[2]), "=r"(r[3]) : "r"(addr));
}
__device__ __forceinline__ void mma16816(float* c, const uint32_t* a,
                                         const uint32_t* b) {
    asm volatile(
        "mma.sync.aligned.m16n8k16.row.col.f32.bf16.bf16.f32 "
        "{%0,%1,%2,%3}, {%4,%5,%6,%7}, {%8,%9}, {%0,%1,%2,%3};"
        : "+f"(c[0]), "+f"(c[1]), "+f"(c[2]), "+f"(c[3])
        : "r"(a[0]), "r"(a[1]), "r"(a[2]), "r"(a[3]), "r"(b[0]), "r"(b[1]));
}
__device__ __forceinline__ uint32_t pack_hi(float x, float y) {
    __nv_bfloat162 h = __floats2bfloat162_rn(x, y);
    return *(uint32_t*)&h;
}

// ------------------------------------------------------------ split fp32 ----
__device__ __forceinline__ void split_body(const float* __restrict__ src,
                                           __nv_bfloat16* __restrict__ hi,
                                           __nv_bfloat16* __restrict__ lo, int i)
{
    float4 a = ((const float4*)src)[i];
    __nv_bfloat16 h0 = __float2bfloat16(a.x);
    __nv_bfloat16 h1 = __float2bfloat16(a.y);
    __nv_bfloat16 h2 = __float2bfloat16(a.z);
    __nv_bfloat16 h3 = __float2bfloat16(a.w);
    __nv_bfloat16 l0 = __float2bfloat16(a.x - __bfloat162float(h0));
    __nv_bfloat16 l1 = __float2bfloat16(a.y - __bfloat162float(h1));
    __nv_bfloat16 l2 = __float2bfloat16(a.z - __bfloat162float(h2));
    __nv_bfloat16 l3 = __float2bfloat16(a.w - __bfloat162float(h3));
    ((__nv_bfloat162*)hi)[2*i]   = __nv_bfloat162(h0, h1);
    ((__nv_bfloat162*)hi)[2*i+1] = __nv_bfloat162(h2, h3);
    ((__nv_bfloat162*)lo)[2*i]   = __nv_bfloat162(l0, l1);
    ((__nv_bfloat162*)lo)[2*i+1] = __nv_bfloat162(l2, l3);
}

__global__ void __launch_bounds__(256) split_kernel(
    const float* __restrict__ src, __nv_bfloat16* __restrict__ hi,
    __nv_bfloat16* __restrict__ lo, int n4)
{
    int i = blockIdx.x * blockDim.x + threadIdx.x;
    if (i >= n4) return;
    split_body(src, hi, lo, i);
}

// all four weight matrices in one launch; slot w at offset w*WSZ
__global__ void __launch_bounds__(256) split4_kernel(
    const float* __restrict__ s0, const float* __restrict__ s1,
    const float* __restrict__ s2, const float* __restrict__ s3,
    __nv_bfloat16* __restrict__ hi, __nv_bfloat16* __restrict__ lo, int n4)
{
    int i = blockIdx.x * blockDim.x + threadIdx.x;
    if (i >= n4) return;
    int w = blockIdx.y;
    const float* src = (w == 0) ? s0 : (w == 1) ? s1 : (w == 2) ? s2 : s3;
    split_body(src, hi + (size_t)w * WSZ, lo + (size_t)w * WSZ, i);
}

// --------------------------------------------------- mma.sync bf16 GEMM ----
// Rows packed [hi(64B)|lo(64B)] = 128B, SW128 XOR swizzle (chunk ^= row&7).
// Stage = A(16KB) + B(16KB) = 32KB; 3 stages = 96KB -> 2 CTAs/SM.
#define AREG  16384
#define STGB  32768
#define GSTG  3
#define GSMEM (GSTG*STGB)     /* 98304 */

// Shared mainloop: accumulates C(128x128) for tile (m0,n0); A/B hi-lo packed.
__device__ __forceinline__ void gemm_mainloop(
    const __nv_bfloat16* __restrict__ Ah, const __nv_bfloat16* __restrict__ Al,
    const __nv_bfloat16* __restrict__ Bh, const __nv_bfloat16* __restrict__ Bl,
    uint32_t sb, int tid, int m0, int n0, float acc[4][4][4])
{
    const int lane = tid & 31, wid = tid >> 5;
    const int wm = wid >> 2, wn = wid & 3;
    const int S = DM / 32;

    const int lr = tid >> 1;
    const uint32_t lsx = (uint32_t)(lr & 7) << 4;
    const int lj0 = (tid & 1) * 2;
    const size_t ga = (size_t)(m0 + lr) * DM;
    const size_t gb = (size_t)(n0 + lr) * DM;

    auto load_stage = [&](int s) {
        const int k0 = s * 32;
        const uint32_t ab = sb + (s % GSTG) * STGB + (uint32_t)lr * 128;
        const uint32_t bbs = ab + AREG;
        const char* pah = (const char*)(Ah + ga + k0);
        const char* pal = (const char*)(Al + ga + k0);
        const char* pbh = (const char*)(Bh + gb + k0);
        const char* pbl = (const char*)(Bl + gb + k0);
        #pragma unroll
        for (int q = 0; q < 2; ++q) {
            const int j = lj0 + q;
            cp16(ab  + (((uint32_t)(j    ) << 4) ^ lsx), pah + j*16);
            cp16(ab  + (((uint32_t)(j + 4) << 4) ^ lsx), pal + j*16);
            cp16(bbs + (((uint32_t)(j    ) << 4) ^ lsx), pbh + j*16);
            cp16(bbs + (((uint32_t)(j + 4) << 4) ^ lsx), pbl + j*16);
        }
        cp_commit();
    };

    load_stage(0);
    load_stage(1);

    const uint32_t sx = (uint32_t)(lane & 7) << 4;
    const uint32_t a_row = (uint32_t)(wm*64 + (lane & 15)) * 128;
    const uint32_t a_k   = (uint32_t)(lane >> 4) << 4;
    const uint32_t b_row = (uint32_t)(wn*32 + ((lane >> 4) & 1)*8 + (lane & 7)) * 128;
    const uint32_t b_k   = (uint32_t)((lane >> 3) & 1) << 4;

    for (int s = 0; s < S; ++s) {
        if (s == S - 1) cp_wait<0>(); else cp_wait<1>();
        __syncthreads();
        if (s + 2 < S) load_stage(s + 2);

        const uint32_t Abase = sb + (s % GSTG) * STGB;
        const uint32_t Bbase = Abase + AREG;
        #pragma unroll
        for (int kk = 0; kk < 2; ++kk) {
            const uint32_t kb = (uint32_t)kk * 32;
            uint32_t ah[4][4], bh[2][4];
            #pragma unroll
            for (int i = 0; i < 4; ++i)
                ldm4(ah[i], Abase + a_row + i*2048 + ((kb + a_k) ^ sx));
            #pragma unroll
            for (int p = 0; p < 2; ++p)
                ldm4(bh[p], Bbase + b_row + p*2048 + ((kb + b_k) ^ sx));
            #pragma unroll
            for (int i = 0; i < 4; ++i)
                #pragma unroll
                for (int j = 0; j < 4; ++j)
                    mma16816(acc[i][j], ah[i], &bh[j >> 1][(j & 1) * 2]);
            {
                uint32_t al[4][4];
                #pragma unroll
                for (int i = 0; i < 4; ++i)
                    ldm4(al[i], Abase + a_row + i*2048 + ((64 + kb + a_k) ^ sx));
                #pragma unroll
                for (int i = 0; i < 4; ++i)
                    #pragma unroll
                    for (int j = 0; j < 4; ++j)
                        mma16816(acc[i][j], al[i], &bh[j >> 1][(j & 1) * 2]);
            }
            {
                uint32_t bl[2][4];
                #pragma unroll
                for (int p = 0; p < 2; ++p)
                    ldm4(bl[p], Bbase + b_row + p*2048 + ((64 + kb + b_k) ^ sx));
                #pragma unroll
                for (int i = 0; i < 4; ++i)
                    #pragma unroll
                    for (int j = 0; j < 4; ++j)
                        mma16816(acc[i][j], ah[i], &bl[j >> 1][(j & 1) * 2]);
            }
        }
    }
}

// stage C through smem (stride 132 floats)
__device__ __forceinline__ void stage_epilogue(char* smem, int tid,
                                               float acc[4][4][4])
{
    __syncthreads();
    float* Cs = (float*)smem;
    const int lane = tid & 31, wid = tid >> 5;
    const int wm = wid >> 2, wn = wid & 3;
    const int frow = wm*64 + (lane >> 2);
    const int fcol = wn*32 + (lane & 3) * 2;
    #pragma unroll
    for (int i = 0; i < 4; ++i)
        #pragma unroll
        for (int j = 0; j < 4; ++j) {
            *(float2*)&Cs[(frow + i*16    )*132 + fcol + j*8] =
                make_float2(acc[i][j][0], acc[i][j][1]);
            *(float2*)&Cs[(frow + i*16 + 8)*132 + fcol + j*8] =
                make_float2(acc[i][j][2], acc[i][j][3]);
        }
    __syncthreads();
}

// ---- fused QKV projection: grid.z selects weight / dst / RoPE ----
__global__ void __launch_bounds__(256, 2) gemm_qkv(
    const __nv_bfloat16* __restrict__ Ah, const __nv_bfloat16* __restrict__ Al,
    const __nv_bfloat16* __restrict__ W4h, const __nv_bfloat16* __restrict__ W4l,
    __nv_bfloat16* __restrict__ Qh, __nv_bfloat16* __restrict__ Ql,
    __nv_bfloat16* __restrict__ Kh, __nv_bfloat16* __restrict__ Kl,
    __nv_bfloat16* __restrict__ Vh, __nv_bfloat16* __restrict__ Vl,
    const float* __restrict__ cosc, const float* __restrict__ sinc)
{
    extern __shared__ char smem[];
    const uint32_t sb = smem_u32(smem);
    const int tid = threadIdx.x;
    const int m0 = blockIdx.y * 128, n0 = blockIdx.x * 128;
    const int z = blockIdx.z;

    const __nv_bfloat16* Bh = W4h + (size_t)z * WSZ;
    const __nv_bfloat16* Bl = W4l + (size_t)z * WSZ;

    float acc[4][4][4];
    #pragma unroll
    for (int i = 0; i < 4; ++i)
        #pragma unroll
        for (int j = 0; j < 4; ++j)
            #pragma unroll
            for (int q = 0; q < 4; ++q) acc[i][j][q] = 0.f;

    gemm_mainloop(Ah, Al, Bh, Bl, sb, tid, m0, n0, acc);
    stage_epilogue(smem, tid, acc);

    __nv_bfloat16 *Ch, *Cl;
    if (z == 0)      { Ch = Qh; Cl = Ql; }
    else if (z == 1) { Ch = Kh; Cl = Kl; }
    else             { Ch = Vh; Cl = Vl; }
    const bool dorope = (z < 2);

    float* Cs = (float*)smem;
    const int row  = tid >> 1;
    const int half = tid & 1;
    const int grow = m0 + row;
    const int h = n0 >> 7;
    int bb = grow >> 11, l = grow & (LL - 1);
    size_t ofs = (((size_t)(bb * NH + h)) * LL + l) * HD;

    #pragma unroll
    for (int c0 = 0; c0 < 32; c0 += 4) {
        const int col = half*32 + c0;
        float a0[4], a1[4];
        #pragma unroll
        for (int q = 0; q < 4; ++q) {
            a0[q] = Cs[row*132 + col + q];
            a1[q] = Cs[row*132 + col + 64 + q];
        }
        if (dorope) {
            #pragma unroll
            for (int q = 0; q < 4; ++q) {
                float c1 = cosc[h*HD + col + q];
                float s1 = sinc[h*HD + col + q];
                float c2 = cosc[h*HD + col + q + 64];
                float s2 = sinc[h*HD + col + q + 64];
                float v0 = a0[q], v1 = a1[q];
                a0[q] = v0*c1 - v1*s1;
                a1[q] = v1*c2 + v0*s2;
            }
        }
        #pragma unroll
        for (int q = 0; q < 4; q += 2) {
            __nv_bfloat162 h0 = __floats2bfloat162_rn(a0[q], a0[q+1]);
            float2 f0 = __bfloat1622float2(h0);
            __nv_bfloat162 l0 = __floats2bfloat162_rn(a0[q]-f0.x, a0[q+1]-f0.y);
            *(__nv_bfloat162*)(Ch + ofs + col + q) = h0;
            *(__nv_bfloat162*)(Cl + ofs + col + q) = l0;
            __nv_bfloat162 h1 = __floats2bfloat162_rn(a1[q], a1[q+1]);
            float2 f1 = __bfloat1622float2(h1);
            __nv_bfloat162 l1 = __floats2bfloat162_rn(a1[q]-f1.x, a1[q+1]-f1.y);
            *(__nv_bfloat162*)(Ch + ofs + col + 64 + q) = h1;
            *(__nv_bfloat162*)(Cl + ofs + col + 64 + q) = l1;
        }
    }
}

// ---- O-projection: fp32 output ----
__global__ void __launch_bounds__(256, 2) gemm_out(
    const __nv_bfloat16* __restrict__ Ah, const __nv_bfloat16* __restrict__ Al,
    const __nv_bfloat16* __restrict__ Bh, const __nv_bfloat16* __restrict__ Bl,
    float* __restrict__ C)
{
    extern __shared__ char smem[];
    const uint32_t sb = smem_u32(smem);
    const int tid = threadIdx.x;
    const int m0 = blockIdx.y * 128, n0 = blockIdx.x * 128;

    float acc[4][4][4];
    #pragma unroll
    for (int i = 0; i < 4; ++i)
        #pragma unroll
        for (int j = 0; j < 4; ++j)
            #pragma unroll
            for (int q = 0; q < 4; ++q) acc[i][j][q] = 0.f;

    gemm_mainloop(Ah, Al, Bh, Bl, sb, tid, m0, n0, acc);
    stage_epilogue(smem, tid, acc);

    float* Cs = (float*)smem;
    const int row  = tid >> 1;
    const int half = tid & 1;
    float* dst = C + (size_t)(m0 + row) * DM + n0;
    #pragma unroll
    for (int c0 = 0; c0 < 32; c0 += 4) {
        const int col = half*32 + c0;
        *(float4*)(dst + col)      = *(float4*)&Cs[row*132 + col];
        *(float4*)(dst + col + 64) = *(float4*)&Cs[row*132 + col + 64];
    }
}

// ---------------------------------------------------- bf16 flash attention --
#define APITCH 272
#define AT_QH 0
#define AT_QL 34816
#define AT_K  69632               /* + bs*34816 ; lo at +17408 */
#define AT_V  139264
#define AT_MASK 208896
#define AT_SMEM (208896 + 8192)   /* 217088 */

__global__ void __launch_bounds__(256) attn_mma(
    const __nv_bfloat16* __restrict__ Qh, const __nv_bfloat16* __restrict__ Ql,
    const __nv_bfloat16* __restrict__ Kh, const __nv_bfloat16* __restrict__ Kl,
    const __nv_bfloat16* __restrict__ Vh, const __nv_bfloat16* __restrict__ Vl,
    const int* __restrict__ mask,
    __nv_bfloat16* __restrict__ Oh, __nv_bfloat16* __restrict__ Ol)
{
    extern __shared__ char sm[];
    const uint32_t sb = smem_u32(sm);
    const int tid = threadIdx.x, lane = tid & 31, wid = tid >> 5;
    const int q0 = (int)(gridDim.x - 1 - blockIdx.x) * 128;   // heavy first
    const int h = blockIdx.y, b = blockIdx.z;
    const size_t hb = ((size_t)(b*NH + h)) * LL * HD;
    const __nv_bfloat16 *pQh = Qh+hb, *pQl = Ql+hb;
    const __nv_bfloat16 *pKh = Kh+hb, *pKl = Kl+hb;
    const __nv_bfloat16 *pVh = Vh+hb, *pVl = Vl+hb;
    int* msk = (int*)(sm + AT_MASK);

    for (int i = tid; i < LL; i += 256) msk[i] = mask[b*LL + i];

    {
        int row = tid >> 1;
        const char* gqh = (const char*)(pQh + (size_t)(q0+row)*HD);
        const char* gql = (const char*)(pQl + (size_t)(q0+row)*HD);
        uint32_t dq = sb + row * APITCH;
        #pragma unroll
        for (int t = 0; t < 8; ++t) {
            int c = (tid & 1) + 2*t;
            cp16(dq + c*16,           gqh + c*16);
            cp16(dq + AT_QL + c*16,   gql + c*16);
        }
    }

    auto load_kv = [&](int kt, int bs) {
        int k0 = kt * 64;
        int row = tid >> 2;
        const char* gkh = (const char*)(pKh + (size_t)(k0+row)*HD);
        const char* gkl = (const char*)(pKl + (size_t)(k0+row)*HD);
        const char* gvh = (const char*)(pVh + (size_t)(k0+row)*HD);
        const char* gvl = (const char*)(pVl + (size_t)(k0+row)*HD);
        uint32_t dk = sb + AT_K + bs*34816 + row*APITCH;
        uint32_t dv = sb + AT_V + bs*34816 + row*APITCH;
        #pragma unroll
        for (int t = 0; t < 4; ++t) {
            int c = (tid & 3) + 4*t;
            cp16(dk + c*16,         gkh + c*16);
            cp16(dk + 17408 + c*16, gkl + c*16);
            cp16(dv + c*16,         gvh + c*16);
            cp16(dv + 17408 + c*16, gvl + c*16);
        }
        cp_commit();
    };

    const int ntiles = q0/64 + 2;
    load_kv(0, 0);
    load_kv(1, 1);

    float oacc[16][4];
    #pragma unroll
    for (int u = 0; u < 16; ++u)
        #pragma unroll
        for (int q = 0; q < 4; ++q) oacc[u][q] = 0.f;
    float m_i[2] = {-1e30f, -1e30f}, l_i[2] = {0.f, 0.f};

    const uint32_t a_hi = sb + (wid*16 + (lane & 15))*APITCH + (lane >> 4)*16;
    const uint32_t a_lo = a_hi + AT_QL;
    const uint32_t b_off = (uint32_t)((((lane >> 4) & 1)*8 + (lane & 7))*APITCH
                                      + ((lane >> 3) & 1)*16);
    const uint32_t v_off = (uint32_t)((lane & 15)*APITCH + (lane >> 4)*16);
    const float scale = 0.08838834764831845f;
    const int r0 = lane >> 2;

    for (int kt = 0; kt < ntiles; ++kt) {
        const int bs = kt & 1;
        const int k0 = kt * 64;
        if (kt == ntiles - 1) cp_wait<0>(); else cp_wait<1>();
        __syncthreads();

        const uint32_t kh_base = sb + AT_K + bs*34816;
        const uint32_t vh_base = sb + AT_V + bs*34816;

        float sacc[8][4];
        #pragma unroll
        for (int j = 0; j < 8; ++j)
            #pragma unroll
            for (int q = 0; q < 4; ++q) sacc[j][q] = 0.f;

        #pragma unroll 2
        for (int ks = 0; ks < 8; ++ks) {
            const uint32_t ka = ks * 32;
            uint32_t ah[4], al[4], bh[4][4];
            ldm4(ah, a_hi + ka);
            ldm4(al, a_lo + ka);
            #pragma unroll
            for (int p = 0; p < 4; ++p)
                ldm4(bh[p], kh_base + b_off + p*16*APITCH + ka);
            #pragma unroll
            for (int j = 0; j < 8; ++j) {
                uint32_t* bb = &bh[j >> 1][(j & 1) * 2];
                mma16816(sacc[j], ah, bb);
                mma16816(sacc[j], al, bb);
            }
            uint32_t bl[4][4];
            #pragma unroll
            for (int p = 0; p < 4; ++p)
                ldm4(bl[p], kh_base + 17408 + b_off + p*16*APITCH + ka);
            #pragma unroll
            for (int j = 0; j < 8; ++j)
                mma16816(sacc[j], ah, &bl[j >> 1][(j & 1) * 2]);
        }

        #pragma unroll
        for (int rr = 0; rr < 2; ++rr) {
            const int qr = q0 + wid*16 + r0 + rr*8;
            float tm = -1e30f;
            #pragma unroll
            for (int j = 0; j < 8; ++j) {
                #pragma unroll
                for (int e = 0; e < 2; ++e) {
                    int col = k0 + j*8 + (lane & 3)*2 + e;
                    float v = sacc[j][rr*2 + e] * scale;
                    if (col > qr || msk[col] == 0) v = -1e15f;
                    sacc[j][rr*2 + e] = v;
                    tm = fmaxf(tm, v);
                }
            }
            tm = fmaxf(tm, __shfl_xor_sync(0xffffffffu, tm, 1));
            tm = fmaxf(tm, __shfl_xor_sync(0xffffffffu, tm, 2));
            float mnew = fmaxf(m_i[rr], tm);
            float sc = __expf(m_i[rr] - mnew);
            m_i[rr] = mnew;
            float rs = 0.f;
            #pragma unroll
            for (int j = 0; j < 8; ++j) {
                #pragma unroll
                for (int e = 0; e < 2; ++e) {
                    float p = __expf(sacc[j][rr*2 + e] - mnew);
                    sacc[j][rr*2 + e] = p;
                    rs += p;
                }
            }
            rs += __shfl_xor_sync(0xffffffffu, rs, 1);
            rs += __shfl_xor_sync(0xffffffffu, rs, 2);
            l_i[rr] = l_i[rr] * sc + rs;
            #pragma unroll
            for (int u = 0; u < 16; ++u) {
                oacc[u][rr*2]     *= sc;
                oacc[u][rr*2 + 1] *= sc;
            }
        }

        #pragma unroll 1
        for (int t = 0; t < 4; ++t) {
            uint32_t pah[4], pal[4];
            #pragma unroll
            for (int idx = 0; idx < 4; ++idx) {
                int j = 2*t + (idx >> 1);
                int o = (idx & 1) * 2;
                float p0 = sacc[j][o], p1 = sacc[j][o + 1];
                __nv_bfloat162 hv = __floats2bfloat162_rn(p0, p1);
                float2 hf = __bfloat1622float2(hv);
                pah[idx] = *(uint32_t*)&hv;
                pal[idx] = pack_hi(p0 - hf.x, p1 - hf.y);
            }
            #pragma unroll
            for (int u = 0; u < 8; ++u) {
                uint32_t vh[4], vl[4];
                uint32_t addr = vh_base + t*16*APITCH + u*32 + v_off;
                ldm4t(vh, addr);
                ldm4t(vl, addr + 17408);
                mma16816(oacc[2*u],     pah, vh);
                mma16816(oacc[2*u],     pal, vh);
                mma16816(oacc[2*u],     pah, vl);
                mma16816(oacc[2*u + 1], pah, vh + 2);
                mma16816(oacc[2*u + 1], pal, vh + 2);
                mma16816(oacc[2*u + 1], pah, vl + 2);
            }
        }

        if (kt + 2 < ntiles) {
            __syncthreads();
            load_kv(kt + 2, bs);
        }
    }

    #pragma unroll
    for (int rr = 0; rr < 2; ++rr) {
        float inv = 1.0f / l_i[rr];
        int lrow = q0 + wid*16 + r0 + rr*8;
        size_t base = ((size_t)(b*LL + lrow)) * DM + h*HD;
        #pragma unroll
        for (int u = 0; u < 16; ++u) {
            int col = u*8 + (lane & 3)*2;
            float p0 = oacc[u][rr*2]     * inv;
            float p1 = oacc[u][rr*2 + 1] * inv;
            __nv_bfloat162 hv = __floats2bfloat162_rn(p0, p1);
            float2 hf = __bfloat1622float2(hv);
            __nv_bfloat162 lv = __floats2bfloat162_rn(p0 - hf.x, p1 - hf.y);
            *(__nv_bfloat162*)(Oh + base + col) = hv;
            *(__nv_bfloat162*)(Ol + base + col) = lv;
        }
    }
}

// ---------------------------------------------------------------------------
extern "C" void kernel_launch(void* const* d_in, const int* in_sizes, int n_in,
                              void* d_out, int out_size)
{
    const float* hidden = (const float*)d_in[0];
    const int*   mask   = (const int*)  d_in[1];
    const float* Wq     = (const float*)d_in[2];
    const float* Wk     = (const float*)d_in[3];
    const float* Wv     = (const float*)d_in[4];
    const float* Wo     = (const float*)d_in[5];
    const float* cosc   = (const float*)d_in[6];
    const float* sinc   = (const float*)d_in[7];
    float* out = (float*)d_out;

    __nv_bfloat16 *Ahp, *Alp, *W4hp, *W4lp, *Qhp, *Qlp, *Khp, *Klp, *Vhp, *Vlp;
    cudaGetSymbolAddress((void**)&Ahp,  g_Ah);
    cudaGetSymbolAddress((void**)&Alp,  g_Al);
    cudaGetSymbolAddress((void**)&W4hp, g_W4h);
    cudaGetSymbolAddress((void**)&W4lp, g_W4l);
    cudaGetSymbolAddress((void**)&Qhp,  g_Qh);
    cudaGetSymbolAddress((void**)&Qlp,  g_Ql);
    cudaGetSymbolAddress((void**)&Khp,  g_Kh);
    cudaGetSymbolAddress((void**)&Klp,  g_Kl);
    cudaGetSymbolAddress((void**)&Vhp,  g_Vh);
    cudaGetSymbolAddress((void**)&Vlp,  g_Vl);

    cudaFuncSetAttribute(gemm_qkv, cudaFuncAttributeMaxDynamicSharedMemorySize, GSMEM);
    cudaFuncSetAttribute(gemm_out, cudaFuncAttributeMaxDynamicSharedMemorySize, GSMEM);
    cudaFuncSetAttribute(attn_mma, cudaFuncAttributeMaxDynamicSharedMemorySize, AT_SMEM);

    const int nA4 = MROWS*DM/4, nW4 = DM*DM/4;

    // splits: hidden + all four weights (Wo included, off the critical path)
    split_kernel<<<(nA4+255)/256, 256>>>(hidden, Ahp, Alp, nA4);
    {
        dim3 gs((nW4+255)/256, 4);
        split4_kernel<<<gs, 256>>>(Wq, Wk, Wv, Wo, W4hp, W4lp, nW4);
    }

    // fused Q/K/V projections (+RoPE for Q,K) in one launch
    {
        dim3 gg(DM/128, MROWS/128, 3);
        gemm_qkv<<<gg, 256, GSMEM>>>(Ahp, Alp, W4hp, W4lp,
                                     Qhp, Qlp, Khp, Klp, Vhp, Vlp, cosc, sinc);
    }

    dim3 ga(LL/128, NH, BB);
    attn_mma<<<ga, 256, AT_SMEM>>>(Qhp, Qlp, Khp, Klp, Vhp, Vlp, mask, Ahp, Alp);

    {
        dim3 gg(DM/128, MROWS/128);
        gemm_out<<<gg, 256, GSMEM>>>(Ahp, Alp, W4hp + 3*WSZ, W4lp + 3*WSZ, out);
    }
}

// round 11
// speedup vs baseline: 2.7185x; 1.0230x over previous
#include <cuda_runtime.h>
#include <cuda_bf16.h>
#include <cstdint>
#include <math.h>

#define BB 2
#define LL 2048
#define DM 2048
#define NH 16
#define HD 128
#define MROWS (BB*LL)   // 4096
#define WSZ ((size_t)DM*(size_t)DM)

// ---------------------------------------------------------------- scratch ---
__device__ __nv_bfloat16 g_Ah[MROWS*DM];
__device__ __nv_bfloat16 g_Al[MROWS*DM];
__device__ __nv_bfloat16 g_W4h[4*DM*DM];
__device__ __nv_bfloat16 g_W4l[4*DM*DM];
__device__ __nv_bfloat16 g_Qh[MROWS*DM];
__device__ __nv_bfloat16 g_Ql[MROWS*DM];
__device__ __nv_bfloat16 g_Kh[MROWS*DM];
__device__ __nv_bfloat16 g_Kl[MROWS*DM];
__device__ __nv_bfloat16 g_Vh[MROWS*DM];
__device__ __nv_bfloat16 g_Vl[MROWS*DM];

// ------------------------------------------------------------ ptx helpers ---
__device__ __forceinline__ uint32_t smem_u32(const void* p) {
    uint32_t a;
    asm("{ .reg .u64 t; cvta.to.shared.u64 t, %1; cvt.u32.u64 %0, t; }"
        : "=r"(a) : "l"(p));
    return a;
}
__device__ __forceinline__ void cp16(uint32_t d, const void* s) {
    asm volatile("cp.async.cg.shared.global [%0], [%1], 16;" :: "r"(d), "l"(s));
}
__device__ __forceinline__ void cp_commit() {
    asm volatile("cp.async.commit_group;" ::: "memory");
}
template<int N> __device__ __forceinline__ void cp_wait() {
    asm volatile("cp.async.wait_group %0;" :: "n"(N) : "memory");
}
__device__ __forceinline__ void ldm4(uint32_t* r, uint32_t addr) {
    asm volatile("ldmatrix.sync.aligned.m8n8.x4.shared.b16 {%0,%1,%2,%3}, [%4];"
                 : "=r"(r[0]), "=r"(r[1]), "=r"(r[2]), "=r"(r[3]) : "r"(addr));
}
__device__ __forceinline__ void ldm4t(uint32_t* r, uint32_t addr) {
    asm volatile("ldmatrix.sync.aligned.m8n8.x4.trans.shared.b16 {%0,%1,%2,%3}, [%4];"
                 : "=r"(r[0]), "=r"(r[1]), "=r"(r[2]), "=r"(r[3]) : "r"(addr));
}
__device__ __forceinline__ void mma16816(float* c, const uint32_t* a,
                                         const uint32_t* b) {
    asm volatile(
        "mma.sync.aligned.m16n8k16.row.col.f32.bf16.bf16.f32 "
        "{%0,%1,%2,%3}, {%4,%5,%6,%7}, {%8,%9}, {%0,%1,%2,%3};"
        : "+f"(c[0]), "+f"(c[1]), "+f"(c[2]), "+f"(c[3])
        : "r"(a[0]), "r"(a[1]), "r"(a[2]), "r"(a[3]), "r"(b[0]), "r"(b[1]));
}
__device__ __forceinline__ uint32_t pack_hi(float x, float y) {
    __nv_bfloat162 h = __floats2bfloat162_rn(x, y);
    return *(uint32_t*)&h;
}

// ------------------------------------------------------------ split fp32 ----
__device__ __forceinline__ void split_body(const float* __restrict__ src,
                                           __nv_bfloat16* __restrict__ hi,
                                           __nv_bfloat16* __restrict__ lo, int i)
{
    float4 a = ((const float4*)src)[i];
    __nv_bfloat16 h0 = __float2bfloat16(a.x);
    __nv_bfloat16 h1 = __float2bfloat16(a.y);
    __nv_bfloat16 h2 = __float2bfloat16(a.z);
    __nv_bfloat16 h3 = __float2bfloat16(a.w);
    __nv_bfloat16 l0 = __float2bfloat16(a.x - __bfloat162float(h0));
    __nv_bfloat16 l1 = __float2bfloat16(a.y - __bfloat162float(h1));
    __nv_bfloat16 l2 = __float2bfloat16(a.z - __bfloat162float(h2));
    __nv_bfloat16 l3 = __float2bfloat16(a.w - __bfloat162float(h3));
    ((__nv_bfloat162*)hi)[2*i]   = __nv_bfloat162(h0, h1);
    ((__nv_bfloat162*)hi)[2*i+1] = __nv_bfloat162(h2, h3);
    ((__nv_bfloat162*)lo)[2*i]   = __nv_bfloat162(l0, l1);
    ((__nv_bfloat162*)lo)[2*i+1] = __nv_bfloat162(l2, l3);
}

__global__ void __launch_bounds__(256) split_kernel(
    const float* __restrict__ src, __nv_bfloat16* __restrict__ hi,
    __nv_bfloat16* __restrict__ lo, int n4)
{
    int i = blockIdx.x * blockDim.x + threadIdx.x;
    if (i >= n4) return;
    split_body(src, hi, lo, i);
}

__global__ void __launch_bounds__(256) split4_kernel(
    const float* __restrict__ s0, const float* __restrict__ s1,
    const float* __restrict__ s2, const float* __restrict__ s3,
    __nv_bfloat16* __restrict__ hi, __nv_bfloat16* __restrict__ lo, int n4)
{
    int i = blockIdx.x * blockDim.x + threadIdx.x;
    if (i >= n4) return;
    int w = blockIdx.y;
    const float* src = (w == 0) ? s0 : (w == 1) ? s1 : (w == 2) ? s2 : s3;
    split_body(src, hi + (size_t)w * WSZ, lo + (size_t)w * WSZ, i);
}

// --------------------------------------------------- mma.sync bf16 GEMM ----
#define AREG  16384
#define STGB  32768
#define GSTG  3
#define GSMEM (GSTG*STGB)     /* 98304 */

__device__ __forceinline__ void gemm_mainloop(
    const __nv_bfloat16* __restrict__ Ah, const __nv_bfloat16* __restrict__ Al,
    const __nv_bfloat16* __restrict__ Bh, const __nv_bfloat16* __restrict__ Bl,
    uint32_t sb, int tid, int m0, int n0, float acc[4][4][4])
{
    const int lane = tid & 31, wid = tid >> 5;
    const int wm = wid >> 2, wn = wid & 3;
    const int S = DM / 32;

    const int lr = tid >> 1;
    const uint32_t lsx = (uint32_t)(lr & 7) << 4;
    const int lj0 = (tid & 1) * 2;
    const size_t ga = (size_t)(m0 + lr) * DM;
    const size_t gb = (size_t)(n0 + lr) * DM;

    auto load_stage = [&](int s) {
        const int k0 = s * 32;
        const uint32_t ab = sb + (s % GSTG) * STGB + (uint32_t)lr * 128;
        const uint32_t bbs = ab + AREG;
        const char* pah = (const char*)(Ah + ga + k0);
        const char* pal = (const char*)(Al + ga + k0);
        const char* pbh = (const char*)(Bh + gb + k0);
        const char* pbl = (const char*)(Bl + gb + k0);
        #pragma unroll
        for (int q = 0; q < 2; ++q) {
            const int j = lj0 + q;
            cp16(ab  + (((uint32_t)(j    ) << 4) ^ lsx), pah + j*16);
            cp16(ab  + (((uint32_t)(j + 4) << 4) ^ lsx), pal + j*16);
            cp16(bbs + (((uint32_t)(j    ) << 4) ^ lsx), pbh + j*16);
            cp16(bbs + (((uint32_t)(j + 4) << 4) ^ lsx), pbl + j*16);
        }
        cp_commit();
    };

    load_stage(0);
    load_stage(1);

    const uint32_t sx = (uint32_t)(lane & 7) << 4;
    const uint32_t a_row = (uint32_t)(wm*64 + (lane & 15)) * 128;
    const uint32_t a_k   = (uint32_t)(lane >> 4) << 4;
    const uint32_t b_row = (uint32_t)(wn*32 + ((lane >> 4) & 1)*8 + (lane & 7)) * 128;
    const uint32_t b_k   = (uint32_t)((lane >> 3) & 1) << 4;

    for (int s = 0; s < S; ++s) {
        if (s == S - 1) cp_wait<0>(); else cp_wait<1>();
        __syncthreads();
        if (s + 2 < S) load_stage(s + 2);

        const uint32_t Abase = sb + (s % GSTG) * STGB;
        const uint32_t Bbase = Abase + AREG;
        #pragma unroll
        for (int kk = 0; kk < 2; ++kk) {
            const uint32_t kb = (uint32_t)kk * 32;
            uint32_t ah[4][4], bh[2][4];
            #pragma unroll
            for (int i = 0; i < 4; ++i)
                ldm4(ah[i], Abase + a_row + i*2048 + ((kb + a_k) ^ sx));
            #pragma unroll
            for (int p = 0; p < 2; ++p)
                ldm4(bh[p], Bbase + b_row + p*2048 + ((kb + b_k) ^ sx));
            #pragma unroll
            for (int i = 0; i < 4; ++i)
                #pragma unroll
                for (int j = 0; j < 4; ++j)
                    mma16816(acc[i][j], ah[i], &bh[j >> 1][(j & 1) * 2]);
            {
                uint32_t al[4][4];
                #pragma unroll
                for (int i = 0; i < 4; ++i)
                    ldm4(al[i], Abase + a_row + i*2048 + ((64 + kb + a_k) ^ sx));
                #pragma unroll
                for (int i = 0; i < 4; ++i)
                    #pragma unroll
                    for (int j = 0; j < 4; ++j)
                        mma16816(acc[i][j], al[i], &bh[j >> 1][(j & 1) * 2]);
            }
            {
                uint32_t bl[2][4];
                #pragma unroll
                for (int p = 0; p < 2; ++p)
                    ldm4(bl[p], Bbase + b_row + p*2048 + ((64 + kb + b_k) ^ sx));
                #pragma unroll
                for (int i = 0; i < 4; ++i)
                    #pragma unroll
                    for (int j = 0; j < 4; ++j)
                        mma16816(acc[i][j], ah[i], &bl[j >> 1][(j & 1) * 2]);
            }
        }
    }
}

__device__ __forceinline__ void stage_epilogue(char* smem, int tid,
                                               float acc[4][4][4])
{
    __syncthreads();
    float* Cs = (float*)smem;
    const int lane = tid & 31, wid = tid >> 5;
    const int wm = wid >> 2, wn = wid & 3;
    const int frow = wm*64 + (lane >> 2);
    const int fcol = wn*32 + (lane & 3) * 2;
    #pragma unroll
    for (int i = 0; i < 4; ++i)
        #pragma unroll
        for (int j = 0; j < 4; ++j) {
            *(float2*)&Cs[(frow + i*16    )*132 + fcol + j*8] =
                make_float2(acc[i][j][0], acc[i][j][1]);
            *(float2*)&Cs[(frow + i*16 + 8)*132 + fcol + j*8] =
                make_float2(acc[i][j][2], acc[i][j][3]);
        }
    __syncthreads();
}

// ---- fused QKV projection: grid.z selects weight / dst / RoPE ----
__global__ void __launch_bounds__(256, 2) gemm_qkv(
    const __nv_bfloat16* __restrict__ Ah, const __nv_bfloat16* __restrict__ Al,
    const __nv_bfloat16* __restrict__ W4h, const __nv_bfloat16* __restrict__ W4l,
    __nv_bfloat16* __restrict__ Qh, __nv_bfloat16* __restrict__ Ql,
    __nv_bfloat16* __restrict__ Kh, __nv_bfloat16* __restrict__ Kl,
    __nv_bfloat16* __restrict__ Vh, __nv_bfloat16* __restrict__ Vl,
    const float* __restrict__ cosc, const float* __restrict__ sinc)
{
    extern __shared__ char smem[];
    const uint32_t sb = smem_u32(smem);
    const int tid = threadIdx.x;
    const int m0 = blockIdx.y * 128, n0 = blockIdx.x * 128;
    const int z = blockIdx.z;

    const __nv_bfloat16* Bh = W4h + (size_t)z * WSZ;
    const __nv_bfloat16* Bl = W4l + (size_t)z * WSZ;

    float acc[4][4][4];
    #pragma unroll
    for (int i = 0; i < 4; ++i)
        #pragma unroll
        for (int j = 0; j < 4; ++j)
            #pragma unroll
            for (int q = 0; q < 4; ++q) acc[i][j][q] = 0.f;

    gemm_mainloop(Ah, Al, Bh, Bl, sb, tid, m0, n0, acc);
    stage_epilogue(smem, tid, acc);

    __nv_bfloat16 *Ch, *Cl;
    if (z == 0)      { Ch = Qh; Cl = Ql; }
    else if (z == 1) { Ch = Kh; Cl = Kl; }
    else             { Ch = Vh; Cl = Vl; }
    const bool dorope = (z < 2);

    float* Cs = (float*)smem;
    const int row  = tid >> 1;
    const int half = tid & 1;
    const int grow = m0 + row;
    const int h = n0 >> 7;
    int bb = grow >> 11, l = grow & (LL - 1);
    size_t ofs = (((size_t)(bb * NH + h)) * LL + l) * HD;

    #pragma unroll
    for (int c0 = 0; c0 < 32; c0 += 4) {
        const int col = half*32 + c0;
        float a0[4], a1[4];
        #pragma unroll
        for (int q = 0; q < 4; ++q) {
            a0[q] = Cs[row*132 + col + q];
            a1[q] = Cs[row*132 + col + 64 + q];
        }
        if (dorope) {
            #pragma unroll
            for (int q = 0; q < 4; ++q) {
                float c1 = cosc[h*HD + col + q];
                float s1 = sinc[h*HD + col + q];
                float c2 = cosc[h*HD + col + q + 64];
                float s2 = sinc[h*HD + col + q + 64];
                float v0 = a0[q], v1 = a1[q];
                a0[q] = v0*c1 - v1*s1;
                a1[q] = v1*c2 + v0*s2;
            }
        }
        #pragma unroll
        for (int q = 0; q < 4; q += 2) {
            __nv_bfloat162 h0 = __floats2bfloat162_rn(a0[q], a0[q+1]);
            float2 f0 = __bfloat1622float2(h0);
            __nv_bfloat162 l0 = __floats2bfloat162_rn(a0[q]-f0.x, a0[q+1]-f0.y);
            *(__nv_bfloat162*)(Ch + ofs + col + q) = h0;
            *(__nv_bfloat162*)(Cl + ofs + col + q) = l0;
            __nv_bfloat162 h1 = __floats2bfloat162_rn(a1[q], a1[q+1]);
            float2 f1 = __bfloat1622float2(h1);
            __nv_bfloat162 l1 = __floats2bfloat162_rn(a1[q]-f1.x, a1[q+1]-f1.y);
            *(__nv_bfloat162*)(Ch + ofs + col + 64 + q) = h1;
            *(__nv_bfloat162*)(Cl + ofs + col + 64 + q) = l1;
        }
    }
}

// ---- O-projection: fp32 output ----
__global__ void __launch_bounds__(256, 2) gemm_out(
    const __nv_bfloat16* __restrict__ Ah, const __nv_bfloat16* __restrict__ Al,
    const __nv_bfloat16* __restrict__ Bh, const __nv_bfloat16* __restrict__ Bl,
    float* __restrict__ C)
{
    extern __shared__ char smem[];
    const uint32_t sb = smem_u32(smem);
    const int tid = threadIdx.x;
    const int m0 = blockIdx.y * 128, n0 = blockIdx.x * 128;

    float acc[4][4][4];
    #pragma unroll
    for (int i = 0; i < 4; ++i)
        #pragma unroll
        for (int j = 0; j < 4; ++j)
            #pragma unroll
            for (int q = 0; q < 4; ++q) acc[i][j][q] = 0.f;

    gemm_mainloop(Ah, Al, Bh, Bl, sb, tid, m0, n0, acc);
    stage_epilogue(smem, tid, acc);

    float* Cs = (float*)smem;
    const int row  = tid >> 1;
    const int half = tid & 1;
    float* dst = C + (size_t)(m0 + row) * DM + n0;
    #pragma unroll
    for (int c0 = 0; c0 < 32; c0 += 4) {
        const int col = half*32 + c0;
        *(float4*)(dst + col)      = *(float4*)&Cs[row*132 + col];
        *(float4*)(dst + col + 64) = *(float4*)&Cs[row*132 + col + 64];
    }
}

// ---------------------------------------------------- bf16 flash attention --
// 512 threads / 16 warps. Warp pair (rowg, half): 16 q-rows x 32-key half.
// Pair softmax combine via smem partials + named barriers.
#define APITCH 272
#define AT_QL 34816
#define AT_K  69632               /* + bs*34816 ; lo at +17408 */
#define AT_V  139264
#define AT_MASK 208896
#define AT_RED  217088            /* pmax[128][2], psum[128][2] */
#define AT_SMEM 219136

__global__ void __launch_bounds__(512) attn_mma(
    const __nv_bfloat16* __restrict__ Qh, const __nv_bfloat16* __restrict__ Ql,
    const __nv_bfloat16* __restrict__ Kh, const __nv_bfloat16* __restrict__ Kl,
    const __nv_bfloat16* __restrict__ Vh, const __nv_bfloat16* __restrict__ Vl,
    const int* __restrict__ mask,
    __nv_bfloat16* __restrict__ Oh, __nv_bfloat16* __restrict__ Ol)
{
    extern __shared__ char sm[];
    const uint32_t sb = smem_u32(sm);
    const int tid = threadIdx.x, lane = tid & 31, wid = tid >> 5;
    const int rowg = wid >> 1;            // 0..7: 16-row group
    const int half = wid & 1;             // key half (32 cols)
    const int q0 = (int)(gridDim.x - 1 - blockIdx.x) * 128;   // heavy first
    const int h = blockIdx.y, b = blockIdx.z;
    const size_t hb = ((size_t)(b*NH + h)) * LL * HD;
    const __nv_bfloat16 *pQh = Qh+hb, *pQl = Ql+hb;
    const __nv_bfloat16 *pKh = Kh+hb, *pKl = Kl+hb;
    const __nv_bfloat16 *pVh = Vh+hb, *pVl = Vl+hb;
    int* msk = (int*)(sm + AT_MASK);
    float* pmax = (float*)(sm + AT_RED);      // [128][2]
    float* psum = pmax + 256;                 // [128][2]

    for (int i = tid; i < LL; i += 512) msk[i] = mask[b*LL + i];

    // Q tile (128 rows x 128 hd, hi+lo): 4 cp16 each per component
    {
        int row = tid >> 2;
        int c0 = tid & 3;
        const char* gqh = (const char*)(pQh + (size_t)(q0+row)*HD);
        const char* gql = (const char*)(pQl + (size_t)(q0+row)*HD);
        uint32_t dq = sb + row * APITCH;
        #pragma unroll
        for (int t = 0; t < 4; ++t) {
            int c = c0 + 4*t;
            cp16(dq + c*16,         gqh + c*16);
            cp16(dq + AT_QL + c*16, gql + c*16);
        }
    }

    auto load_kv = [&](int kt, int bs) {
        int k0 = kt * 64;
        int row = tid >> 3;          // 0..63
        int c0 = tid & 7;
        const char* gkh = (const char*)(pKh + (size_t)(k0+row)*HD);
        const char* gkl = (const char*)(pKl + (size_t)(k0+row)*HD);
        const char* gvh = (const char*)(pVh + (size_t)(k0+row)*HD);
        const char* gvl = (const char*)(pVl + (size_t)(k0+row)*HD);
        uint32_t dk = sb + AT_K + bs*34816 + row*APITCH;
        uint32_t dv = sb + AT_V + bs*34816 + row*APITCH;
        #pragma unroll
        for (int t = 0; t < 2; ++t) {
            int c = c0 + 8*t;
            cp16(dk + c*16,         gkh + c*16);
            cp16(dk + 17408 + c*16, gkl + c*16);
            cp16(dv + c*16,         gvh + c*16);
            cp16(dv + 17408 + c*16, gvl + c*16);
        }
        cp_commit();
    };

    const int ntiles = q0/64 + 2;
    load_kv(0, 0);
    load_kv(1, 1);

    float oacc[16][4];
    #pragma unroll
    for (int u = 0; u < 16; ++u)
        #pragma unroll
        for (int q = 0; q < 4; ++q) oacc[u][q] = 0.f;
    float m_i[2] = {-1e30f, -1e30f}, l_i[2] = {0.f, 0.f};

    const uint32_t a_hi = sb + (rowg*16 + (lane & 15))*APITCH + (lane >> 4)*16;
    const uint32_t a_lo = a_hi + AT_QL;
    const uint32_t b_off = (uint32_t)((half*32 + ((lane >> 4) & 1)*8 + (lane & 7))*APITCH
                                      + ((lane >> 3) & 1)*16);
    const uint32_t v_off = (uint32_t)((lane & 15)*APITCH + (lane >> 4)*16);
    const float scale = 0.08838834764831845f;   // 1/sqrt(128)
    const int r0 = lane >> 2;
    const int bar_id = rowg + 1;

    for (int kt = 0; kt < ntiles; ++kt) {
        const int bs = kt & 1;
        const int k0 = kt * 64;
        if (kt == ntiles - 1) cp_wait<0>(); else cp_wait<1>();
        __syncthreads();

        const uint32_t kh_base = sb + AT_K + bs*34816;
        const uint32_t vh_base = sb + AT_V + bs*34816;

        // ---- S = Q K^T, warp's 32-key half (3-term) ----
        float sacc[4][4];
        #pragma unroll
        for (int j = 0; j < 4; ++j)
            #pragma unroll
            for (int q = 0; q < 4; ++q) sacc[j][q] = 0.f;

        #pragma unroll 2
        for (int ks = 0; ks < 8; ++ks) {
            const uint32_t ka = ks * 32;
            uint32_t ah[4], al[4], bh[2][4];
            ldm4(ah, a_hi + ka);
            ldm4(al, a_lo + ka);
            #pragma unroll
            for (int p = 0; p < 2; ++p)
                ldm4(bh[p], kh_base + b_off + p*16*APITCH + ka);
            #pragma unroll
            for (int j = 0; j < 4; ++j) {
                uint32_t* bb = &bh[j >> 1][(j & 1) * 2];
                mma16816(sacc[j], ah, bb);
                mma16816(sacc[j], al, bb);
            }
            uint32_t bl[2][4];
            #pragma unroll
            for (int p = 0; p < 2; ++p)
                ldm4(bl[p], kh_base + 17408 + b_off + p*16*APITCH + ka);
            #pragma unroll
            for (int j = 0; j < 4; ++j)
                mma16816(sacc[j], ah, &bl[j >> 1][(j & 1) * 2]);
        }

        // ---- softmax: mask + partial max ----
        #pragma unroll
        for (int rr = 0; rr < 2; ++rr) {
            const int lr = rowg*16 + r0 + rr*8;
            const int qr = q0 + lr;
            float tm = -1e30f;
            #pragma unroll
            for (int j = 0; j < 4; ++j) {
                #pragma unroll
                for (int e = 0; e < 2; ++e) {
                    int col = k0 + half*32 + j*8 + (lane & 3)*2 + e;
                    float v = sacc[j][rr*2 + e] * scale;
                    if (col > qr || msk[col] == 0) v = -1e15f;
                    sacc[j][rr*2 + e] = v;
                    tm = fmaxf(tm, v);
                }
            }
            tm = fmaxf(tm, __shfl_xor_sync(0xffffffffu, tm, 1));
            tm = fmaxf(tm, __shfl_xor_sync(0xffffffffu, tm, 2));
            if ((lane & 3) == 0) pmax[lr*2 + half] = tm;
        }
        asm volatile("bar.sync %0, 64;" :: "r"(bar_id) : "memory");

        // ---- combined max, exp, partial sum ----
        float scv[2];
        #pragma unroll
        for (int rr = 0; rr < 2; ++rr) {
            const int lr = rowg*16 + r0 + rr*8;
            float tm = fmaxf(pmax[lr*2], pmax[lr*2 + 1]);
            float mnew = fmaxf(m_i[rr], tm);
            scv[rr] = __expf(m_i[rr] - mnew);
            m_i[rr] = mnew;
            float rs = 0.f;
            #pragma unroll
            for (int j = 0; j < 4; ++j) {
                #pragma unroll
                for (int e = 0; e < 2; ++e) {
                    float p = __expf(sacc[j][rr*2 + e] - mnew);
                    sacc[j][rr*2 + e] = p;
                    rs += p;
                }
            }
            rs += __shfl_xor_sync(0xffffffffu, rs, 1);
            rs += __shfl_xor_sync(0xffffffffu, rs, 2);
            if ((lane & 3) == 0) psum[lr*2 + half] = rs;
            #pragma unroll
            for (int u = 0; u < 16; ++u) {
                oacc[u][rr*2]     *= scv[rr];
                oacc[u][rr*2 + 1] *= scv[rr];
            }
        }
        asm volatile("bar.sync %0, 64;" :: "r"(bar_id) : "memory");

        #pragma unroll
        for (int rr = 0; rr < 2; ++rr) {
            const int lr = rowg*16 + r0 + rr*8;
            l_i[rr] = l_i[rr] * scv[rr] + psum[lr*2] + psum[lr*2 + 1];
        }

        // ---- O += P V over warp's 32 keys (3-term; P split in-register) ----
        #pragma unroll 1
        for (int t = 0; t < 2; ++t) {
            uint32_t pah[4], pal[4];
            #pragma unroll
            for (int idx = 0; idx < 4; ++idx) {
                int j = 2*t + (idx >> 1);
                int o = (idx & 1) * 2;
                float p0 = sacc[j][o], p1 = sacc[j][o + 1];
                __nv_bfloat162 hv = __floats2bfloat162_rn(p0, p1);
                float2 hf = __bfloat1622float2(hv);
                pah[idx] = *(uint32_t*)&hv;
                pal[idx] = pack_hi(p0 - hf.x, p1 - hf.y);
            }
            #pragma unroll
            for (int u = 0; u < 8; ++u) {
                uint32_t vh[4], vl[4];
                uint32_t addr = vh_base + (half*32 + t*16)*APITCH + u*32 + v_off;
                ldm4t(vh, addr);
                ldm4t(vl, addr + 17408);
                mma16816(oacc[2*u],     pah, vh);
                mma16816(oacc[2*u],     pal, vh);
                mma16816(oacc[2*u],     pah, vl);
                mma16816(oacc[2*u + 1], pah, vh + 2);
                mma16816(oacc[2*u + 1], pal, vh + 2);
                mma16816(oacc[2*u + 1], pah, vl + 2);
            }
        }

        if (kt + 2 < ntiles) {
            __syncthreads();
            load_kv(kt + 2, bs);
        }
    }

    // ---- combine key-halves via smem (reuse K region), then epilogue ----
    __syncthreads();
    float* Osm = (float*)(sm + AT_K);       // 128 x 128 fp32 = 64KB
    if (half == 1) {
        #pragma unroll
        for (int rr = 0; rr < 2; ++rr) {
            int r = rowg*16 + r0 + rr*8;
            #pragma unroll
            for (int u = 0; u < 16; ++u) {
                int col = u*8 + (lane & 3)*2;
                Osm[r*128 + col]     = oacc[u][rr*2];
                Osm[r*128 + col + 1] = oacc[u][rr*2 + 1];
            }
        }
    }
    __syncthreads();
    if (half == 0) {
        #pragma unroll
        for (int rr = 0; rr < 2; ++rr) {
            float inv = 1.0f / l_i[rr];
            int r = rowg*16 + r0 + rr*8;
            int lrow = q0 + r;
            size_t base = ((size_t)(b*LL + lrow)) * DM + h*HD;
            #pragma unroll
            for (int u = 0; u < 16; ++u) {
                int col = u*8 + (lane & 3)*2;
                float p0 = (oacc[u][rr*2]     + Osm[r*128 + col])     * inv;
                float p1 = (oacc[u][rr*2 + 1] + Osm[r*128 + col + 1]) * inv;
                __nv_bfloat162 hv = __floats2bfloat162_rn(p0, p1);
                float2 hf = __bfloat1622float2(hv);
                __nv_bfloat162 lv = __floats2bfloat162_rn(p0 - hf.x, p1 - hf.y);
                *(__nv_bfloat162*)(Oh + base + col) = hv;
                *(__nv_bfloat162*)(Ol + base + col) = lv;
            }
        }
    }
}

// ---------------------------------------------------------------------------
extern "C" void kernel_launch(void* const* d_in, const int* in_sizes, int n_in,
                              void* d_out, int out_size)
{
    const float* hidden = (const float*)d_in[0];
    const int*   mask   = (const int*)  d_in[1];
    const float* Wq     = (const float*)d_in[2];
    const float* Wk     = (const float*)d_in[3];
    const float* Wv     = (const float*)d_in[4];
    const float* Wo     = (const float*)d_in[5];
    const float* cosc   = (const float*)d_in[6];
    const float* sinc   = (const float*)d_in[7];
    float* out = (float*)d_out;

    __nv_bfloat16 *Ahp, *Alp, *W4hp, *W4lp, *Qhp, *Qlp, *Khp, *Klp, *Vhp, *Vlp;
    cudaGetSymbolAddress((void**)&Ahp,  g_Ah);
    cudaGetSymbolAddress((void**)&Alp,  g_Al);
    cudaGetSymbolAddress((void**)&W4hp, g_W4h);
    cudaGetSymbolAddress((void**)&W4lp, g_W4l);
    cudaGetSymbolAddress((void**)&Qhp,  g_Qh);
    cudaGetSymbolAddress((void**)&Qlp,  g_Ql);
    cudaGetSymbolAddress((void**)&Khp,  g_Kh);
    cudaGetSymbolAddress((void**)&Klp,  g_Kl);
    cudaGetSymbolAddress((void**)&Vhp,  g_Vh);
    cudaGetSymbolAddress((void**)&Vlp,  g_Vl);

    cudaFuncSetAttribute(gemm_qkv, cudaFuncAttributeMaxDynamicSharedMemorySize, GSMEM);
    cudaFuncSetAttribute(gemm_out, cudaFuncAttributeMaxDynamicSharedMemorySize, GSMEM);
    cudaFuncSetAttribute(attn_mma, cudaFuncAttributeMaxDynamicSharedMemorySize, AT_SMEM);

    const int nA4 = MROWS*DM/4, nW4 = DM*DM/4;

    split_kernel<<<(nA4+255)/256, 256>>>(hidden, Ahp, Alp, nA4);
    {
        dim3 gs((nW4+255)/256, 4);
        split4_kernel<<<gs, 256>>>(Wq, Wk, Wv, Wo, W4hp, W4lp, nW4);
    }

    {
        dim3 gg(DM/128, MROWS/128, 3);
        gemm_qkv<<<gg, 256, GSMEM>>>(Ahp, Alp, W4hp, W4lp,
                                     Qhp, Qlp, Khp, Klp, Vhp, Vlp, cosc, sinc);
    }

    dim3 ga(LL/128, NH, BB);
    attn_mma<<<ga, 512, AT_SMEM>>>(Qhp, Qlp, Khp, Klp, Vhp, Vlp, mask, Ahp, Alp);

    {
        dim3 gg(DM/128, MROWS/128);
        gemm_out<<<gg, 256, GSMEM>>>(Ahp, Alp, W4hp + 3*WSZ, W4lp + 3*WSZ, out);
    }
}